// round 6
// baseline (speedup 1.0000x reference)
#include <cuda_runtime.h>
#include <math.h>

// ---------------------------------------------------------------------------
// Problem constants
//   G=8192 gaussians, BS=1, 3 tokens, GFD=32, ATTN=512, H=8 heads, HD=64
//   image_features [256,64,64], K = 12 sample points (6 fixed + 6 learned)
// ---------------------------------------------------------------------------
#define NG      8192
#define NROW    (NG*3)        // 24576 (gaussian,token) rows
#define ATTN    512
#define GFD     32
#define NHEAD   8
#define HDIM    64
#define IMGW    64
#define IMGH    64
#define NPIX    (IMGW*IMGH)   // 4096
#define CIMG    256
#define NK      12

// Scratch (static device globals: allocation-free per harness rules)
__device__ float g_kv[NPIX * 1024];     // [pix][0:512 K, 512:1024 V]  (16 MB)
__device__ float g_q[NROW * ATTN];      // q_full                       (50 MB)
__device__ float g_attn[NROW * ATTN];   // attention output             (50 MB)

__constant__ float c_fix[6][3] = {
    {0.f,0.f,0.f},{1.f,0.f,0.f},{0.f,1.f,0.f},
    {0.f,0.f,1.f},{-1.f,0.f,0.f},{0.f,-1.f,0.f}};

__device__ __forceinline__ float sigm_clamped(float x) {
    x = fminf(fmaxf(x, -9.21f), 9.21f);
    return 1.0f / (1.0f + expf(-x));
}

// ---------------------------------------------------------------------------
// Kernel 1: KV maps.  C[a,pix] = sum_c Wkv[a,c] * img[c,pix]
//   a in [0,1024): rows 0..511 from Wk, 512..1023 from Wv.
//   Written transposed into g_kv[pix*1024 + a].
// ---------------------------------------------------------------------------
__global__ void __launch_bounds__(256) kv_gemm(
    const float* __restrict__ Wk, const float* __restrict__ Wv,
    const float* __restrict__ img)
{
    __shared__ float As[64][17];   // a x k (padded)
    __shared__ float Bs[16][64];   // k x pix

    const int aBase = blockIdx.y * 64;
    const int pBase = blockIdx.x * 64;
    const int tid = threadIdx.x;
    const int tx = tid & 15, ty = tid >> 4;

    float acc[4][4] = {};

    for (int kk = 0; kk < CIMG; kk += 16) {
        #pragma unroll
        for (int i = tid; i < 64 * 16; i += 256) {
            int a = i >> 4, k = i & 15;
            int ga = aBase + a;
            float v = (ga < 512) ? Wk[ga * CIMG + kk + k]
                                 : Wv[(ga - 512) * CIMG + kk + k];
            As[a][k] = v;
        }
        #pragma unroll
        for (int i = tid; i < 16 * 64; i += 256) {
            int k = i >> 6, p = i & 63;
            Bs[k][p] = img[(kk + k) * NPIX + pBase + p];
        }
        __syncthreads();
        #pragma unroll
        for (int k = 0; k < 16; k++) {
            float av[4], bv[4];
            #pragma unroll
            for (int i = 0; i < 4; i++) av[i] = As[ty * 4 + i][k];
            #pragma unroll
            for (int j = 0; j < 4; j++) bv[j] = Bs[k][tx * 4 + j];
            #pragma unroll
            for (int i = 0; i < 4; i++)
                #pragma unroll
                for (int j = 0; j < 4; j++) acc[i][j] += av[i] * bv[j];
        }
        __syncthreads();
    }
    #pragma unroll
    for (int i = 0; i < 4; i++)
        #pragma unroll
        for (int j = 0; j < 4; j++)
            g_kv[(size_t)(pBase + tx * 4 + j) * 1024 + aBase + ty * 4 + i] = acc[i][j];
}

// ---------------------------------------------------------------------------
// Kernel 2: Q projection.  g_q[row, a] = sum_f feat[row, f] * Wq[f, a]
//   M=24576, K=32, N=512
// ---------------------------------------------------------------------------
__global__ void __launch_bounds__(256) q_gemm(
    const float* __restrict__ feat, const float* __restrict__ Wq)
{
    __shared__ float As[64][33];   // rows x k
    __shared__ float Bs[32][64];   // k x cols

    const int rBase = blockIdx.y * 64;
    const int cBase = blockIdx.x * 64;
    const int tid = threadIdx.x;
    const int tx = tid & 15, ty = tid >> 4;

    #pragma unroll
    for (int i = tid; i < 64 * 32; i += 256) {
        int r = i >> 5, k = i & 31;
        As[r][k] = feat[(size_t)(rBase + r) * 32 + k];
    }
    #pragma unroll
    for (int i = tid; i < 32 * 64; i += 256) {
        int k = i >> 6, c = i & 63;
        Bs[k][c] = Wq[(size_t)k * ATTN + cBase + c];
    }
    __syncthreads();

    float acc[4][4] = {};
    #pragma unroll
    for (int k = 0; k < 32; k++) {
        float av[4], bv[4];
        #pragma unroll
        for (int i = 0; i < 4; i++) av[i] = As[ty * 4 + i][k];
        #pragma unroll
        for (int j = 0; j < 4; j++) bv[j] = Bs[k][tx * 4 + j];
        #pragma unroll
        for (int i = 0; i < 4; i++)
            #pragma unroll
            for (int j = 0; j < 4; j++) acc[i][j] += av[i] * bv[j];
    }
    #pragma unroll
    for (int i = 0; i < 4; i++)
        #pragma unroll
        for (int j = 0; j < 4; j++)
            g_q[(size_t)(rBase + ty * 4 + i) * ATTN + cBase + tx * 4 + j] = acc[i][j];
}

// ---------------------------------------------------------------------------
// Kernel 3: fused deformable attention.
//   One block per gaussian (8192 blocks), one warp per head (256 threads).
// ---------------------------------------------------------------------------
__global__ void __launch_bounds__(256) attn_kernel(
    const float* __restrict__ means, const float* __restrict__ scales,
    const float* __restrict__ rots, const float* __restrict__ transforms,
    const float* __restrict__ proj, const float* __restrict__ W_off,
    const float* __restrict__ b_off)
{
    const int g = blockIdx.x;
    const int tid = threadIdx.x;
    const int h = tid >> 5;
    const int lane = tid & 31;

    __shared__ float sq[3 * ATTN];       // q for this gaussian
    __shared__ float sqm[NHEAD][HDIM];   // per-head token-mean query
    __shared__ float slog[NHEAD][18];    // offset logits
    __shared__ float sW[67 * 18];
    __shared__ float sb[18];
    __shared__ float sP[16];
    __shared__ float sMisc[16];          // 0-2 mean_w, 3-11 R(row major), 12-14 scales

    for (int i = tid; i < 3 * ATTN; i += 256) sq[i] = g_q[(size_t)g * 3 * ATTN + i];
    for (int i = tid; i < 67 * 18; i += 256) sW[i] = W_off[i];
    if (tid < 18) sb[tid] = b_off[tid];
    if (tid >= 32 && tid < 48) sP[tid - 32] = proj[tid - 32];
    if (tid == 64) {
        float mx = means[g * 3], my = means[g * 3 + 1], mz = means[g * 3 + 2];
        const float* T = transforms + (size_t)g * 16;
        sMisc[0] = T[0] * mx + T[1] * my + T[2]  * mz + T[3];
        sMisc[1] = T[4] * mx + T[5] * my + T[6]  * mz + T[7];
        sMisc[2] = T[8] * mx + T[9] * my + T[10] * mz + T[11];
        float qw = rots[g * 4], qx = rots[g * 4 + 1], qy = rots[g * 4 + 2], qz = rots[g * 4 + 3];
        float inv = rsqrtf(qw * qw + qx * qx + qy * qy + qz * qz);
        qw *= inv; qx *= inv; qy *= inv; qz *= inv;
        sMisc[3]  = 1.f - 2.f * (qy * qy + qz * qz);
        sMisc[4]  = 2.f * (qx * qy - qw * qz);
        sMisc[5]  = 2.f * (qx * qz + qw * qy);
        sMisc[6]  = 2.f * (qx * qy + qw * qz);
        sMisc[7]  = 1.f - 2.f * (qx * qx + qz * qz);
        sMisc[8]  = 2.f * (qy * qz - qw * qx);
        sMisc[9]  = 2.f * (qx * qz - qw * qy);
        sMisc[10] = 2.f * (qy * qz + qw * qx);
        sMisc[11] = 1.f - 2.f * (qx * qx + qy * qy);
        sMisc[12] = scales[g * 3]; sMisc[13] = scales[g * 3 + 1]; sMisc[14] = scales[g * 3 + 2];
    }
    __syncthreads();

    // per-head token-mean query
    for (int c = lane; c < HDIM; c += 32)
        sqm[h][c] = (sq[h * HDIM + c] + sq[ATTN + h * HDIM + c] + sq[2 * ATTN + h * HDIM + c]) * (1.0f / 3.0f);
    __syncwarp();

    // offset logits: off_in = [mean_w(3), q_mean(64)] @ W_off + b_off
    if (lane < 18) {
        float acc = sb[lane] + sMisc[0] * sW[lane] + sMisc[1] * sW[18 + lane] + sMisc[2] * sW[36 + lane];
        #pragma unroll 8
        for (int c = 0; c < HDIM; c++) acc += sqm[h][c] * sW[(3 + c) * 18 + lane];
        slog[h][lane] = acc;
    }
    __syncwarp();

    const float mw0 = sMisc[0], mw1 = sMisc[1], mw2 = sMisc[2];
    const float sc0 = sMisc[12], sc1 = sMisc[13], sc2 = sMisc[14];
    const int cbase = h * HDIM + lane * 2;

    float ksA[NK], ksB[NK], vsA[NK], vsB[NK];

    #pragma unroll
    for (int k = 0; k < NK; k++) {
        float s0, s1, s2;
        if (k < 6) {
            s0 = c_fix[k][0]; s1 = c_fix[k][1]; s2 = c_fix[k][2];
        } else {
            int b = (k - 6) * 3;
            s0 = sigm_clamped(slog[h][b])     - 0.5f;
            s1 = sigm_clamped(slog[h][b + 1]) - 0.5f;
            s2 = sigm_clamped(slog[h][b + 2]) - 0.5f;
        }
        float o0 = s0 * sc0, o1 = s1 * sc1, o2 = s2 * sc2;
        // world offset = R^T @ o + mean_w   (out_i = sum_j R[j][i]*o_j)
        float wx = sMisc[3] * o0 + sMisc[6] * o1 + sMisc[9]  * o2 + mw0;
        float wy = sMisc[4] * o0 + sMisc[7] * o1 + sMisc[10] * o2 + mw1;
        float wz = sMisc[5] * o0 + sMisc[8] * o1 + sMisc[11] * o2 + mw2;
        float p0 = sP[0] * wx + sP[1] * wy + sP[2]  * wz + sP[3];
        float p1 = sP[4] * wx + sP[5] * wy + sP[6]  * wz + sP[7];
        float p2 = sP[8] * wx + sP[9] * wy + sP[10] * wz + sP[11];
        float z = fmaxf(p2, 1e-5f);
        float xn = fminf(fmaxf(p0 / z * (1.0f / IMGW), 0.0f), 0.9999f);
        float yn = fminf(fmaxf(p1 / z * (1.0f / IMGH), 0.0f), 0.9999f);
        float x = xn * (float)IMGW - 0.5f;
        float y = yn * (float)IMGH - 0.5f;
        float xf = floorf(x), yf = floorf(y);
        int x0 = (int)xf, y0 = (int)yf;
        float fx = x - xf, fy = y - yf;
        float w00 = (1.f - fx) * (1.f - fy), w10 = fx * (1.f - fy);
        float w01 = (1.f - fx) * fy,         w11 = fx * fy;

        float ka = 0.f, kb = 0.f, va = 0.f, vb = 0.f;
        #pragma unroll
        for (int c = 0; c < 4; c++) {
            int cx = x0 + (c & 1), cy = y0 + (c >> 1);
            float w = (c == 0) ? w00 : (c == 1) ? w10 : (c == 2) ? w01 : w11;
            if (cx >= 0 && cx < IMGW && cy >= 0 && cy < IMGH) {
                const float* base = g_kv + (size_t)(cy * IMGW + cx) * 1024 + cbase;
                float2 kk = *(const float2*)(base);
                float2 vv = *(const float2*)(base + 512);
                ka += w * kk.x; kb += w * kk.y;
                va += w * vv.x; vb += w * vv.y;
            }
        }
        ksA[k] = ka; ksB[k] = kb; vsA[k] = va; vsB[k] = vb;
    }

    // per token: scores -> softmax -> output
    for (int t = 0; t < 3; t++) {
        float qa = sq[t * ATTN + cbase], qb = sq[t * ATTN + cbase + 1];
        float sc[NK];
        #pragma unroll
        for (int k = 0; k < NK; k++) {
            float p = qa * ksA[k] + qb * ksB[k];
            #pragma unroll
            for (int o = 16; o > 0; o >>= 1) p += __shfl_xor_sync(0xffffffffu, p, o);
            sc[k] = p * 0.125f;   // HD^-0.5 = 1/8
        }
        float m = sc[0];
        #pragma unroll
        for (int k = 1; k < NK; k++) m = fmaxf(m, sc[k]);
        float e[NK], sum = 0.f;
        #pragma unroll
        for (int k = 0; k < NK; k++) { e[k] = expf(sc[k] - m); sum += e[k]; }
        float inv = 1.0f / sum;
        float oa = 0.f, ob = 0.f;
        #pragma unroll
        for (int k = 0; k < NK; k++) {
            float a = e[k] * inv;
            oa += a * vsA[k]; ob += a * vsB[k];
        }
        float2 o2v; o2v.x = oa; o2v.y = ob;
        *(float2*)(g_attn + (size_t)(g * 3 + t) * ATTN + cbase) = o2v;
    }
}

// ---------------------------------------------------------------------------
// Kernel 4: output projection + residual.
//   out[row, f] = sum_a g_attn[row, a] * Wout[a, f] + b_out[f] + feat[row, f]
//   M=24576, K=512, N=32
// ---------------------------------------------------------------------------
__global__ void __launch_bounds__(256) out_gemm(
    const float* __restrict__ Wout, const float* __restrict__ b_out,
    const float* __restrict__ feat, float* __restrict__ out)
{
    __shared__ float As[64][33];   // rows x kchunk
    __shared__ float Bs[32][33];   // k x col

    const int rBase = blockIdx.x * 64;
    const int tid = threadIdx.x;
    const int tx = tid & 31;       // output col
    const int ty = tid >> 5;       // 0..7

    float acc[8] = {};

    for (int kk = 0; kk < ATTN; kk += 32) {
        #pragma unroll
        for (int i = tid; i < 64 * 32; i += 256) {
            int r = i >> 5, k = i & 31;
            As[r][k] = g_attn[(size_t)(rBase + r) * ATTN + kk + k];
        }
        #pragma unroll
        for (int i = tid; i < 32 * 32; i += 256) {
            int k = i >> 5, c = i & 31;
            Bs[k][c] = Wout[(size_t)(kk + k) * GFD + c];
        }
        __syncthreads();
        #pragma unroll
        for (int r = 0; r < 8; r++) {
            int row = ty * 8 + r;
            #pragma unroll
            for (int k = 0; k < 32; k++) acc[r] += As[row][k] * Bs[k][tx];
        }
        __syncthreads();
    }
    float bo = b_out[tx];
    #pragma unroll
    for (int r = 0; r < 8; r++) {
        int grow = rBase + ty * 8 + r;
        out[(size_t)grow * GFD + tx] = acc[r] + bo + feat[(size_t)grow * GFD + tx];
    }
}

// ---------------------------------------------------------------------------
// Launch
// ---------------------------------------------------------------------------
extern "C" void kernel_launch(void* const* d_in, const int* in_sizes, int n_in,
                              void* d_out, int out_size)
{
    const float* means      = (const float*)d_in[0];
    const float* scales     = (const float*)d_in[1];
    const float* rotations  = (const float*)d_in[2];
    const float* features   = (const float*)d_in[3];
    const float* transforms = (const float*)d_in[4];
    const float* projection = (const float*)d_in[5];
    const float* image_feat = (const float*)d_in[6];
    const float* Wq         = (const float*)d_in[7];
    const float* Wk         = (const float*)d_in[8];
    const float* Wv         = (const float*)d_in[9];
    const float* W_off      = (const float*)d_in[10];
    const float* b_off      = (const float*)d_in[11];
    const float* Wout       = (const float*)d_in[12];
    const float* b_out      = (const float*)d_in[13];
    float* out = (float*)d_out;

    // 1) KV feature maps: [1024 x 4096] GEMM, written pixel-major
    kv_gemm<<<dim3(NPIX / 64, 1024 / 64), 256>>>(Wk, Wv, image_feat);
    // 2) Q projection: [24576 x 512]
    q_gemm<<<dim3(ATTN / 64, NROW / 64), 256>>>(features, Wq);
    // 3) fused offsets + bilinear sampling + attention
    attn_kernel<<<NG, 256>>>(means, scales, rotations, transforms,
                             projection, W_off, b_off);
    // 4) output projection + bias + residual
    out_gemm<<<NROW / 64, 256>>>(Wout, b_out, features, out);
}

// round 7
// speedup vs baseline: 1.0309x; 1.0309x over previous
#include <cuda_runtime.h>
#include <cuda_fp16.h>
#include <math.h>

// ---------------------------------------------------------------------------
// Problem constants
//   G=8192 gaussians, BS=1, 3 tokens, GFD=32, ATTN=512, H=8 heads, HD=64
//   image_features [256,64,64], K = 12 sample points (6 fixed + 6 learned)
// ---------------------------------------------------------------------------
#define NG      8192
#define NROW    (NG*3)        // 24576 (gaussian,token) rows
#define ATTN    512
#define GFD     32
#define NHEAD   8
#define HDIM    64
#define IMGW    64
#define IMGH    64
#define NPIX    (IMGW*IMGH)   // 4096
#define CIMG    256
#define NK      12

// Scratch (static device globals: allocation-free per harness rules)
__device__ __half2 g_kvh[NPIX * 512];   // [pix][a/2], a in [0,1024): K then V (8 MB)
__device__ float g_q[NROW * ATTN];      // q_full                       (50 MB)
__device__ float g_attn[NROW * ATTN];   // attention output             (50 MB)

__constant__ float c_fix[6][3] = {
    {0.f,0.f,0.f},{1.f,0.f,0.f},{0.f,1.f,0.f},
    {0.f,0.f,1.f},{-1.f,0.f,0.f},{0.f,-1.f,0.f}};

__device__ __forceinline__ float sigm_clamped(float x) {
    x = fminf(fmaxf(x, -9.21f), 9.21f);
    return 1.0f / (1.0f + expf(-x));
}

// ---------------------------------------------------------------------------
// Kernel 1: KV maps.  C[a,pix] = sum_c Wkv[a,c] * img[c,pix]
//   a in [0,1024): rows 0..511 from Wk, 512..1023 from Wv.
//   Written transposed + fp16-packed into g_kvh[pix*512 + a/2].
//   Block tile: 128 (a) x 64 (pix); thread tile 8x4; 256 threads.
// ---------------------------------------------------------------------------
__global__ void __launch_bounds__(256) kv_gemm(
    const float* __restrict__ Wk, const float* __restrict__ Wv,
    const float* __restrict__ img)
{
    __shared__ float As[128][17];   // a x k (padded)
    __shared__ float Bs[16][64];    // k x pix

    const int aBase = blockIdx.y * 128;
    const int pBase = blockIdx.x * 64;
    const int tid = threadIdx.x;
    const int tx = tid & 15;        // pix group (x4)
    const int ty = tid >> 4;        // a group (x8)

    float acc[8][4] = {};

    for (int kk = 0; kk < CIMG; kk += 16) {
        #pragma unroll
        for (int i = tid; i < 128 * 16; i += 256) {
            int a = i >> 4, k = i & 15;
            int ga = aBase + a;
            float v = (ga < 512) ? Wk[ga * CIMG + kk + k]
                                 : Wv[(ga - 512) * CIMG + kk + k];
            As[a][k] = v;
        }
        #pragma unroll
        for (int i = tid; i < 16 * 64; i += 256) {
            int k = i >> 6, p = i & 63;
            Bs[k][p] = img[(kk + k) * NPIX + pBase + p];
        }
        __syncthreads();
        #pragma unroll
        for (int k = 0; k < 16; k++) {
            float av[8], bv[4];
            #pragma unroll
            for (int i = 0; i < 8; i++) av[i] = As[ty * 8 + i][k];
            #pragma unroll
            for (int j = 0; j < 4; j++) bv[j] = Bs[k][tx * 4 + j];
            #pragma unroll
            for (int i = 0; i < 8; i++)
                #pragma unroll
                for (int j = 0; j < 4; j++) acc[i][j] += av[i] * bv[j];
        }
        __syncthreads();
    }
    #pragma unroll
    for (int j = 0; j < 4; j++) {
        int pix = pBase + tx * 4 + j;
        size_t base = (size_t)pix * 512 + ((aBase + ty * 8) >> 1);
        #pragma unroll
        for (int p = 0; p < 4; p++)
            g_kvh[base + p] = __floats2half2_rn(acc[2 * p][j], acc[2 * p + 1][j]);
    }
}

// ---------------------------------------------------------------------------
// Kernel 2: Q projection.  g_q[row, a] = sum_f feat[row, f] * Wq[f, a]
//   M=24576, K=32, N=512
// ---------------------------------------------------------------------------
__global__ void __launch_bounds__(256) q_gemm(
    const float* __restrict__ feat, const float* __restrict__ Wq)
{
    __shared__ float As[64][33];   // rows x k
    __shared__ float Bs[32][64];   // k x cols

    const int rBase = blockIdx.y * 64;
    const int cBase = blockIdx.x * 64;
    const int tid = threadIdx.x;
    const int tx = tid & 15, ty = tid >> 4;

    #pragma unroll
    for (int i = tid; i < 64 * 32; i += 256) {
        int r = i >> 5, k = i & 31;
        As[r][k] = feat[(size_t)(rBase + r) * 32 + k];
    }
    #pragma unroll
    for (int i = tid; i < 32 * 64; i += 256) {
        int k = i >> 6, c = i & 63;
        Bs[k][c] = Wq[(size_t)k * ATTN + cBase + c];
    }
    __syncthreads();

    float acc[4][4] = {};
    #pragma unroll
    for (int k = 0; k < 32; k++) {
        float av[4], bv[4];
        #pragma unroll
        for (int i = 0; i < 4; i++) av[i] = As[ty * 4 + i][k];
        #pragma unroll
        for (int j = 0; j < 4; j++) bv[j] = Bs[k][tx * 4 + j];
        #pragma unroll
        for (int i = 0; i < 4; i++)
            #pragma unroll
            for (int j = 0; j < 4; j++) acc[i][j] += av[i] * bv[j];
    }
    #pragma unroll
    for (int i = 0; i < 4; i++)
        #pragma unroll
        for (int j = 0; j < 4; j++)
            g_q[(size_t)(rBase + ty * 4 + i) * ATTN + cBase + tx * 4 + j] = acc[i][j];
}

// ---------------------------------------------------------------------------
// Kernel 3: fused deformable attention.
//   One block per gaussian (8192 blocks), one warp per head (256 threads).
//   KV gathered from fp16-packed g_kvh (L2-resident, 8 MB).
// ---------------------------------------------------------------------------
__global__ void __launch_bounds__(256) attn_kernel(
    const float* __restrict__ means, const float* __restrict__ scales,
    const float* __restrict__ rots, const float* __restrict__ transforms,
    const float* __restrict__ proj, const float* __restrict__ W_off,
    const float* __restrict__ b_off)
{
    const int g = blockIdx.x;
    const int tid = threadIdx.x;
    const int h = tid >> 5;
    const int lane = tid & 31;

    __shared__ float sq[3 * ATTN];       // q for this gaussian
    __shared__ float sqm[NHEAD][HDIM];   // per-head token-mean query
    __shared__ float slog[NHEAD][18];    // offset logits
    __shared__ float sW[67 * 18];
    __shared__ float sb[18];
    __shared__ float sP[16];
    __shared__ float sMisc[16];          // 0-2 mean_w, 3-11 R(row major), 12-14 scales

    for (int i = tid; i < 3 * ATTN; i += 256) sq[i] = g_q[(size_t)g * 3 * ATTN + i];
    for (int i = tid; i < 67 * 18; i += 256) sW[i] = W_off[i];
    if (tid < 18) sb[tid] = b_off[tid];
    if (tid >= 32 && tid < 48) sP[tid - 32] = proj[tid - 32];
    if (tid == 64) {
        float mx = means[g * 3], my = means[g * 3 + 1], mz = means[g * 3 + 2];
        const float* T = transforms + (size_t)g * 16;
        sMisc[0] = T[0] * mx + T[1] * my + T[2]  * mz + T[3];
        sMisc[1] = T[4] * mx + T[5] * my + T[6]  * mz + T[7];
        sMisc[2] = T[8] * mx + T[9] * my + T[10] * mz + T[11];
        float qw = rots[g * 4], qx = rots[g * 4 + 1], qy = rots[g * 4 + 2], qz = rots[g * 4 + 3];
        float inv = rsqrtf(qw * qw + qx * qx + qy * qy + qz * qz);
        qw *= inv; qx *= inv; qy *= inv; qz *= inv;
        sMisc[3]  = 1.f - 2.f * (qy * qy + qz * qz);
        sMisc[4]  = 2.f * (qx * qy - qw * qz);
        sMisc[5]  = 2.f * (qx * qz + qw * qy);
        sMisc[6]  = 2.f * (qx * qy + qw * qz);
        sMisc[7]  = 1.f - 2.f * (qx * qx + qz * qz);
        sMisc[8]  = 2.f * (qy * qz - qw * qx);
        sMisc[9]  = 2.f * (qx * qz - qw * qy);
        sMisc[10] = 2.f * (qy * qz + qw * qx);
        sMisc[11] = 1.f - 2.f * (qx * qx + qy * qy);
        sMisc[12] = scales[g * 3]; sMisc[13] = scales[g * 3 + 1]; sMisc[14] = scales[g * 3 + 2];
    }
    __syncthreads();

    // per-head token-mean query
    for (int c = lane; c < HDIM; c += 32)
        sqm[h][c] = (sq[h * HDIM + c] + sq[ATTN + h * HDIM + c] + sq[2 * ATTN + h * HDIM + c]) * (1.0f / 3.0f);
    __syncwarp();

    // offset logits: off_in = [mean_w(3), q_mean(64)] @ W_off + b_off
    if (lane < 18) {
        float acc = sb[lane] + sMisc[0] * sW[lane] + sMisc[1] * sW[18 + lane] + sMisc[2] * sW[36 + lane];
        #pragma unroll 8
        for (int c = 0; c < HDIM; c++) acc += sqm[h][c] * sW[(3 + c) * 18 + lane];
        slog[h][lane] = acc;
    }
    __syncwarp();

    const float mw0 = sMisc[0], mw1 = sMisc[1], mw2 = sMisc[2];
    const float sc0 = sMisc[12], sc1 = sMisc[13], sc2 = sMisc[14];
    const int cbase = h * HDIM + lane * 2;     // channel pair within K half
    const int hidx = cbase >> 1;               // half2 index within 512

    float ksA[NK], ksB[NK], vsA[NK], vsB[NK];

    #pragma unroll
    for (int k = 0; k < NK; k++) {
        float s0, s1, s2;
        if (k < 6) {
            s0 = c_fix[k][0]; s1 = c_fix[k][1]; s2 = c_fix[k][2];
        } else {
            int b = (k - 6) * 3;
            s0 = sigm_clamped(slog[h][b])     - 0.5f;
            s1 = sigm_clamped(slog[h][b + 1]) - 0.5f;
            s2 = sigm_clamped(slog[h][b + 2]) - 0.5f;
        }
        float o0 = s0 * sc0, o1 = s1 * sc1, o2 = s2 * sc2;
        // world offset = R^T @ o + mean_w   (out_i = sum_j R[j][i]*o_j)
        float wx = sMisc[3] * o0 + sMisc[6] * o1 + sMisc[9]  * o2 + mw0;
        float wy = sMisc[4] * o0 + sMisc[7] * o1 + sMisc[10] * o2 + mw1;
        float wz = sMisc[5] * o0 + sMisc[8] * o1 + sMisc[11] * o2 + mw2;
        float p0 = sP[0] * wx + sP[1] * wy + sP[2]  * wz + sP[3];
        float p1 = sP[4] * wx + sP[5] * wy + sP[6]  * wz + sP[7];
        float p2 = sP[8] * wx + sP[9] * wy + sP[10] * wz + sP[11];
        float z = fmaxf(p2, 1e-5f);
        float xn = fminf(fmaxf(p0 / z * (1.0f / IMGW), 0.0f), 0.9999f);
        float yn = fminf(fmaxf(p1 / z * (1.0f / IMGH), 0.0f), 0.9999f);
        float x = xn * (float)IMGW - 0.5f;
        float y = yn * (float)IMGH - 0.5f;
        float xf = floorf(x), yf = floorf(y);
        int x0 = (int)xf, y0 = (int)yf;
        float fx = x - xf, fy = y - yf;
        float w00 = (1.f - fx) * (1.f - fy), w10 = fx * (1.f - fy);
        float w01 = (1.f - fx) * fy,         w11 = fx * fy;

        float ka = 0.f, kb = 0.f, va = 0.f, vb = 0.f;
        #pragma unroll
        for (int c = 0; c < 4; c++) {
            int cx = x0 + (c & 1), cy = y0 + (c >> 1);
            float w = (c == 0) ? w00 : (c == 1) ? w10 : (c == 2) ? w01 : w11;
            if (cx >= 0 && cx < IMGW && cy >= 0 && cy < IMGH) {
                const __half2* base = g_kvh + (size_t)(cy * IMGW + cx) * 512 + hidx;
                float2 kf = __half22float2(base[0]);
                float2 vf = __half22float2(base[256]);   // V half: a offset +512 -> +256 half2
                ka += w * kf.x; kb += w * kf.y;
                va += w * vf.x; vb += w * vf.y;
            }
        }
        ksA[k] = ka; ksB[k] = kb; vsA[k] = va; vsB[k] = vb;
    }

    // per token: scores -> softmax -> output
    for (int t = 0; t < 3; t++) {
        float qa = sq[t * ATTN + cbase], qb = sq[t * ATTN + cbase + 1];
        float sc[NK];
        #pragma unroll
        for (int k = 0; k < NK; k++) {
            float p = qa * ksA[k] + qb * ksB[k];
            #pragma unroll
            for (int o = 16; o > 0; o >>= 1) p += __shfl_xor_sync(0xffffffffu, p, o);
            sc[k] = p * 0.125f;   // HD^-0.5 = 1/8
        }
        float m = sc[0];
        #pragma unroll
        for (int k = 1; k < NK; k++) m = fmaxf(m, sc[k]);
        float e[NK], sum = 0.f;
        #pragma unroll
        for (int k = 0; k < NK; k++) { e[k] = expf(sc[k] - m); sum += e[k]; }
        float inv = 1.0f / sum;
        float oa = 0.f, ob = 0.f;
        #pragma unroll
        for (int k = 0; k < NK; k++) {
            float a = e[k] * inv;
            oa += a * vsA[k]; ob += a * vsB[k];
        }
        float2 o2v; o2v.x = oa; o2v.y = ob;
        *(float2*)(g_attn + (size_t)(g * 3 + t) * ATTN + cbase) = o2v;
    }
}

// ---------------------------------------------------------------------------
// Kernel 4: output projection + residual.
//   out[row, f] = sum_a g_attn[row, a] * Wout[a, f] + b_out[f] + feat[row, f]
//   M=24576, K=512, N=32.  Block tile 128x32, thread tile 4x4.
// ---------------------------------------------------------------------------
__global__ void __launch_bounds__(256) out_gemm(
    const float* __restrict__ Wout, const float* __restrict__ b_out,
    const float* __restrict__ feat, float* __restrict__ out)
{
    __shared__ float As[128][33];  // rows x kchunk (padded)
    __shared__ float Bs[32][33];   // k x col (padded)

    const int rBase = blockIdx.x * 128;
    const int tid = threadIdx.x;
    const int tx = tid & 7;        // col group (x4) -> 32 cols
    const int ty = tid >> 3;       // row group (x4) -> 128 rows

    float acc[4][4] = {};

    for (int kk = 0; kk < ATTN; kk += 32) {
        #pragma unroll
        for (int i = tid; i < 128 * 32; i += 256) {
            int r = i >> 5, k = i & 31;
            As[r][k] = g_attn[(size_t)(rBase + r) * ATTN + kk + k];
        }
        #pragma unroll
        for (int i = tid; i < 32 * 32; i += 256) {
            int k = i >> 5, c = i & 31;
            Bs[k][c] = Wout[(size_t)(kk + k) * GFD + c];
        }
        __syncthreads();
        #pragma unroll
        for (int k = 0; k < 32; k++) {
            float av[4], bv[4];
            #pragma unroll
            for (int i = 0; i < 4; i++) av[i] = As[ty * 4 + i][k];
            #pragma unroll
            for (int j = 0; j < 4; j++) bv[j] = Bs[k][tx * 4 + j];
            #pragma unroll
            for (int i = 0; i < 4; i++)
                #pragma unroll
                for (int j = 0; j < 4; j++) acc[i][j] += av[i] * bv[j];
        }
        __syncthreads();
    }
    #pragma unroll
    for (int i = 0; i < 4; i++) {
        int grow = rBase + ty * 4 + i;
        #pragma unroll
        for (int j = 0; j < 4; j++) {
            int col = tx * 4 + j;
            out[(size_t)grow * GFD + col] =
                acc[i][j] + b_out[col] + feat[(size_t)grow * GFD + col];
        }
    }
}

// ---------------------------------------------------------------------------
// Launch
// ---------------------------------------------------------------------------
extern "C" void kernel_launch(void* const* d_in, const int* in_sizes, int n_in,
                              void* d_out, int out_size)
{
    const float* means      = (const float*)d_in[0];
    const float* scales     = (const float*)d_in[1];
    const float* rotations  = (const float*)d_in[2];
    const float* features   = (const float*)d_in[3];
    const float* transforms = (const float*)d_in[4];
    const float* projection = (const float*)d_in[5];
    const float* image_feat = (const float*)d_in[6];
    const float* Wq         = (const float*)d_in[7];
    const float* Wk         = (const float*)d_in[8];
    const float* Wv         = (const float*)d_in[9];
    const float* W_off      = (const float*)d_in[10];
    const float* b_off      = (const float*)d_in[11];
    const float* Wout       = (const float*)d_in[12];
    const float* b_out      = (const float*)d_in[13];
    float* out = (float*)d_out;

    // 1) KV feature maps: [1024 x 4096] GEMM, written pixel-major fp16
    kv_gemm<<<dim3(NPIX / 64, 1024 / 128), 256>>>(Wk, Wv, image_feat);
    // 2) Q projection: [24576 x 512]
    q_gemm<<<dim3(ATTN / 64, NROW / 64), 256>>>(features, Wq);
    // 3) fused offsets + bilinear sampling + attention
    attn_kernel<<<NG, 256>>>(means, scales, rotations, transforms,
                             projection, W_off, b_off);
    // 4) output projection + bias + residual
    out_gemm<<<NROW / 128, 256>>>(Wout, b_out, features, out);
}

// round 8
// speedup vs baseline: 1.2238x; 1.1871x over previous
#include <cuda_runtime.h>
#include <cuda_fp16.h>
#include <math.h>

// ---------------------------------------------------------------------------
// Problem constants
//   G=8192 gaussians, BS=1, 3 tokens, GFD=32, ATTN=512, H=8 heads, HD=64
//   image_features [256,64,64], K = 12 sample points (6 fixed + 6 learned)
// ---------------------------------------------------------------------------
#define NG      8192
#define NROW    (NG*3)        // 24576 (gaussian,token) rows
#define ATTN    512
#define GFD     32
#define NHEAD   8
#define HDIM    64
#define IMGW    64
#define IMGH    64
#define NPIX    (IMGW*IMGH)   // 4096
#define CIMG    256
#define NK      12

// Scratch (static device globals: allocation-free per harness rules)
__device__ __half2 g_kvh[NPIX * 512];      // [pix][a/2], a in [0,1024): K then V (8 MB)
__device__ float   g_q[NROW * ATTN];       // q_full                       (50 MB)
__device__ float   g_attn[NROW * ATTN];    // attention output             (50 MB)
__device__ float2  g_samp[NG * NHEAD * NK];// sample coords (x,y) per (g,h,k) (6 MB)

__constant__ float c_fix[6][3] = {
    {0.f,0.f,0.f},{1.f,0.f,0.f},{0.f,1.f,0.f},
    {0.f,0.f,1.f},{-1.f,0.f,0.f},{0.f,-1.f,0.f}};

__device__ __forceinline__ float sigm_clamped(float x) {
    x = fminf(fmaxf(x, -9.21f), 9.21f);
    return 1.0f / (1.0f + expf(-x));
}

// ---------------------------------------------------------------------------
// Kernel 1: KV maps.  C[a,pix] = sum_c Wkv[a,c] * img[c,pix]
//   a in [0,1024): rows 0..511 from Wk, 512..1023 from Wv.
//   Written transposed + fp16-packed into g_kvh[pix*512 + a/2].
// ---------------------------------------------------------------------------
__global__ void __launch_bounds__(256) kv_gemm(
    const float* __restrict__ Wk, const float* __restrict__ Wv,
    const float* __restrict__ img)
{
    __shared__ float As[128][17];   // a x k (padded)
    __shared__ float Bs[16][64];    // k x pix

    const int aBase = blockIdx.y * 128;
    const int pBase = blockIdx.x * 64;
    const int tid = threadIdx.x;
    const int tx = tid & 15;        // pix group (x4)
    const int ty = tid >> 4;        // a group (x8)

    float acc[8][4] = {};

    for (int kk = 0; kk < CIMG; kk += 16) {
        #pragma unroll
        for (int i = tid; i < 128 * 16; i += 256) {
            int a = i >> 4, k = i & 15;
            int ga = aBase + a;
            float v = (ga < 512) ? Wk[ga * CIMG + kk + k]
                                 : Wv[(ga - 512) * CIMG + kk + k];
            As[a][k] = v;
        }
        #pragma unroll
        for (int i = tid; i < 16 * 64; i += 256) {
            int k = i >> 6, p = i & 63;
            Bs[k][p] = img[(kk + k) * NPIX + pBase + p];
        }
        __syncthreads();
        #pragma unroll
        for (int k = 0; k < 16; k++) {
            float av[8], bv[4];
            #pragma unroll
            for (int i = 0; i < 8; i++) av[i] = As[ty * 8 + i][k];
            #pragma unroll
            for (int j = 0; j < 4; j++) bv[j] = Bs[k][tx * 4 + j];
            #pragma unroll
            for (int i = 0; i < 8; i++)
                #pragma unroll
                for (int j = 0; j < 4; j++) acc[i][j] += av[i] * bv[j];
        }
        __syncthreads();
    }
    #pragma unroll
    for (int j = 0; j < 4; j++) {
        int pix = pBase + tx * 4 + j;
        size_t base = (size_t)pix * 512 + ((aBase + ty * 8) >> 1);
        #pragma unroll
        for (int p = 0; p < 4; p++)
            g_kvh[base + p] = __floats2half2_rn(acc[2 * p][j], acc[2 * p + 1][j]);
    }
}

// ---------------------------------------------------------------------------
// Kernel 2: Q projection.  g_q[row, a] = sum_f feat[row, f] * Wq[f, a]
// ---------------------------------------------------------------------------
__global__ void __launch_bounds__(256) q_gemm(
    const float* __restrict__ feat, const float* __restrict__ Wq)
{
    __shared__ float As[64][33];   // rows x k
    __shared__ float Bs[32][64];   // k x cols

    const int rBase = blockIdx.y * 64;
    const int cBase = blockIdx.x * 64;
    const int tid = threadIdx.x;
    const int tx = tid & 15, ty = tid >> 4;

    #pragma unroll
    for (int i = tid; i < 64 * 32; i += 256) {
        int r = i >> 5, k = i & 31;
        As[r][k] = feat[(size_t)(rBase + r) * 32 + k];
    }
    #pragma unroll
    for (int i = tid; i < 32 * 64; i += 256) {
        int k = i >> 6, c = i & 63;
        Bs[k][c] = Wq[(size_t)k * ATTN + cBase + c];
    }
    __syncthreads();

    float acc[4][4] = {};
    #pragma unroll
    for (int k = 0; k < 32; k++) {
        float av[4], bv[4];
        #pragma unroll
        for (int i = 0; i < 4; i++) av[i] = As[ty * 4 + i][k];
        #pragma unroll
        for (int j = 0; j < 4; j++) bv[j] = Bs[k][tx * 4 + j];
        #pragma unroll
        for (int i = 0; i < 4; i++)
            #pragma unroll
            for (int j = 0; j < 4; j++) acc[i][j] += av[i] * bv[j];
    }
    #pragma unroll
    for (int i = 0; i < 4; i++)
        #pragma unroll
        for (int j = 0; j < 4; j++)
            g_q[(size_t)(rBase + ty * 4 + i) * ATTN + cBase + tx * 4 + j] = acc[i][j];
}

// ---------------------------------------------------------------------------
// Kernel 3a: coordinate precompute.
//   One block per gaussian, one warp per head. Computes OffsetNet logits and
//   the 12 continuous sample coords (x,y) per (g,h), stored to g_samp.
// ---------------------------------------------------------------------------
__global__ void __launch_bounds__(256) coord_kernel(
    const float* __restrict__ means, const float* __restrict__ scales,
    const float* __restrict__ rots, const float* __restrict__ transforms,
    const float* __restrict__ proj, const float* __restrict__ W_off,
    const float* __restrict__ b_off)
{
    const int g = blockIdx.x;
    const int tid = threadIdx.x;
    const int h = tid >> 5;
    const int lane = tid & 31;

    __shared__ float sqm[NHEAD][HDIM];   // per-head token-mean query
    __shared__ float slog[NHEAD][18];    // offset logits
    __shared__ float sW[67 * 18];
    __shared__ float sb[18];
    __shared__ float sP[12];
    __shared__ float sMisc[16];          // 0-2 mean_w, 3-11 R(row major), 12-14 scales

    for (int i = tid; i < 67 * 18; i += 256) sW[i] = W_off[i];
    if (tid < 18) sb[tid] = b_off[tid];
    if (tid >= 32 && tid < 44) sP[tid - 32] = proj[tid - 32];
    if (tid == 64) {
        float mx = means[g * 3], my = means[g * 3 + 1], mz = means[g * 3 + 2];
        const float* T = transforms + (size_t)g * 16;
        sMisc[0] = T[0] * mx + T[1] * my + T[2]  * mz + T[3];
        sMisc[1] = T[4] * mx + T[5] * my + T[6]  * mz + T[7];
        sMisc[2] = T[8] * mx + T[9] * my + T[10] * mz + T[11];
        float qw = rots[g * 4], qx = rots[g * 4 + 1], qy = rots[g * 4 + 2], qz = rots[g * 4 + 3];
        float inv = rsqrtf(qw * qw + qx * qx + qy * qy + qz * qz);
        qw *= inv; qx *= inv; qy *= inv; qz *= inv;
        sMisc[3]  = 1.f - 2.f * (qy * qy + qz * qz);
        sMisc[4]  = 2.f * (qx * qy - qw * qz);
        sMisc[5]  = 2.f * (qx * qz + qw * qy);
        sMisc[6]  = 2.f * (qx * qy + qw * qz);
        sMisc[7]  = 1.f - 2.f * (qx * qx + qz * qz);
        sMisc[8]  = 2.f * (qy * qz - qw * qx);
        sMisc[9]  = 2.f * (qx * qz - qw * qy);
        sMisc[10] = 2.f * (qy * qz + qw * qx);
        sMisc[11] = 1.f - 2.f * (qx * qx + qy * qy);
        sMisc[12] = scales[g * 3]; sMisc[13] = scales[g * 3 + 1]; sMisc[14] = scales[g * 3 + 2];
    }

    // per-head token-mean query (2 channels per lane, straight from g_q)
    {
        const float* qg = g_q + (size_t)g * 3 * ATTN + h * HDIM + lane * 2;
        float2 q0 = *(const float2*)(qg);
        float2 q1 = *(const float2*)(qg + ATTN);
        float2 q2 = *(const float2*)(qg + 2 * ATTN);
        sqm[h][lane * 2]     = (q0.x + q1.x + q2.x) * (1.0f / 3.0f);
        sqm[h][lane * 2 + 1] = (q0.y + q1.y + q2.y) * (1.0f / 3.0f);
    }
    __syncthreads();

    // offset logits: off_in = [mean_w(3), q_mean(64)] @ W_off + b_off
    if (lane < 18) {
        float acc = sb[lane] + sMisc[0] * sW[lane] + sMisc[1] * sW[18 + lane] + sMisc[2] * sW[36 + lane];
        #pragma unroll 8
        for (int c = 0; c < HDIM; c++) acc += sqm[h][c] * sW[(3 + c) * 18 + lane];
        slog[h][lane] = acc;
    }
    __syncwarp();

    if (lane < NK) {
        const int k = lane;
        float s0, s1, s2;
        if (k < 6) {
            s0 = c_fix[k][0]; s1 = c_fix[k][1]; s2 = c_fix[k][2];
        } else {
            int b = (k - 6) * 3;
            s0 = sigm_clamped(slog[h][b])     - 0.5f;
            s1 = sigm_clamped(slog[h][b + 1]) - 0.5f;
            s2 = sigm_clamped(slog[h][b + 2]) - 0.5f;
        }
        float o0 = s0 * sMisc[12], o1 = s1 * sMisc[13], o2 = s2 * sMisc[14];
        // world offset = R^T @ o + mean_w
        float wx = sMisc[3] * o0 + sMisc[6] * o1 + sMisc[9]  * o2 + sMisc[0];
        float wy = sMisc[4] * o0 + sMisc[7] * o1 + sMisc[10] * o2 + sMisc[1];
        float wz = sMisc[5] * o0 + sMisc[8] * o1 + sMisc[11] * o2 + sMisc[2];
        float p0 = sP[0] * wx + sP[1] * wy + sP[2]  * wz + sP[3];
        float p1 = sP[4] * wx + sP[5] * wy + sP[6]  * wz + sP[7];
        float p2 = sP[8] * wx + sP[9] * wy + sP[10] * wz + sP[11];
        float z = fmaxf(p2, 1e-5f);
        float xn = fminf(fmaxf(p0 / z * (1.0f / IMGW), 0.0f), 0.9999f);
        float yn = fminf(fmaxf(p1 / z * (1.0f / IMGH), 0.0f), 0.9999f);
        float2 xy;
        xy.x = xn * (float)IMGW - 0.5f;
        xy.y = yn * (float)IMGH - 0.5f;
        g_samp[((size_t)g * NHEAD + h) * NK + k] = xy;
    }
}

// ---------------------------------------------------------------------------
// Kernel 3b: gather + attention.  ONE WARP per (gaussian, head).
//   No shared memory, no block barriers: pure MLP on L2-resident fp16 KV.
// ---------------------------------------------------------------------------
__global__ void __launch_bounds__(256) gather_attn()
{
    const int wid  = (blockIdx.x * 256 + threadIdx.x) >> 5;  // 0..65535
    const int lane = threadIdx.x & 31;
    const int g = wid >> 3;
    const int h = wid & 7;
    const int hidx = h * 32 + lane;            // half2 index for this lane's 2 channels

    const float2* __restrict__ cp = g_samp + (size_t)wid * NK;

    float ksA[NK], ksB[NK], vsA[NK], vsB[NK];

    #pragma unroll
    for (int k = 0; k < NK; k++) {
        float2 xy = cp[k];                      // uniform within warp -> broadcast
        float xf = floorf(xy.x), yf = floorf(xy.y);
        int x0 = (int)xf, y0 = (int)yf;
        float fx = xy.x - xf, fy = xy.y - yf;
        float w00 = (1.f - fx) * (1.f - fy), w10 = fx * (1.f - fy);
        float w01 = (1.f - fx) * fy,         w11 = fx * fy;

        float ka = 0.f, kb = 0.f, va = 0.f, vb = 0.f;
        #pragma unroll
        for (int c = 0; c < 4; c++) {
            int cx = x0 + (c & 1), cy = y0 + (c >> 1);
            float w = (c == 0) ? w00 : (c == 1) ? w10 : (c == 2) ? w01 : w11;
            if (cx >= 0 && cx < IMGW && cy >= 0 && cy < IMGH) {
                const __half2* base = g_kvh + (size_t)(cy * IMGW + cx) * 512 + hidx;
                float2 kf = __half22float2(base[0]);
                float2 vf = __half22float2(base[256]);
                ka += w * kf.x; kb += w * kf.y;
                va += w * vf.x; vb += w * vf.y;
            }
        }
        ksA[k] = ka; ksB[k] = kb; vsA[k] = va; vsB[k] = vb;
    }

    const float* qg = g_q + (size_t)g * 3 * ATTN + h * HDIM + lane * 2;

    #pragma unroll
    for (int t = 0; t < 3; t++) {
        float2 q = *(const float2*)(qg + t * ATTN);
        float sc[NK];
        #pragma unroll
        for (int k = 0; k < NK; k++) {
            float p = q.x * ksA[k] + q.y * ksB[k];
            #pragma unroll
            for (int o = 16; o > 0; o >>= 1) p += __shfl_xor_sync(0xffffffffu, p, o);
            sc[k] = p * 0.125f;   // HD^-0.5 = 1/8
        }
        float m = sc[0];
        #pragma unroll
        for (int k = 1; k < NK; k++) m = fmaxf(m, sc[k]);
        float e[NK], sum = 0.f;
        #pragma unroll
        for (int k = 0; k < NK; k++) { e[k] = expf(sc[k] - m); sum += e[k]; }
        float inv = 1.0f / sum;
        float oa = 0.f, ob = 0.f;
        #pragma unroll
        for (int k = 0; k < NK; k++) {
            float a = e[k] * inv;
            oa += a * vsA[k]; ob += a * vsB[k];
        }
        float2 o2v; o2v.x = oa; o2v.y = ob;
        *(float2*)(g_attn + (size_t)(g * 3 + t) * ATTN + h * HDIM + lane * 2) = o2v;
    }
}

// ---------------------------------------------------------------------------
// Kernel 4: output projection + residual.
//   out[row, f] = sum_a g_attn[row, a] * Wout[a, f] + b_out[f] + feat[row, f]
// ---------------------------------------------------------------------------
__global__ void __launch_bounds__(256) out_gemm(
    const float* __restrict__ Wout, const float* __restrict__ b_out,
    const float* __restrict__ feat, float* __restrict__ out)
{
    __shared__ float As[128][33];  // rows x kchunk (padded)
    __shared__ float Bs[32][33];   // k x col (padded)

    const int rBase = blockIdx.x * 128;
    const int tid = threadIdx.x;
    const int tx = tid & 7;        // col group (x4) -> 32 cols
    const int ty = tid >> 3;       // row group (x4) -> 128 rows

    float acc[4][4] = {};

    for (int kk = 0; kk < ATTN; kk += 32) {
        #pragma unroll
        for (int i = tid; i < 128 * 32; i += 256) {
            int r = i >> 5, k = i & 31;
            As[r][k] = g_attn[(size_t)(rBase + r) * ATTN + kk + k];
        }
        #pragma unroll
        for (int i = tid; i < 32 * 32; i += 256) {
            int k = i >> 5, c = i & 31;
            Bs[k][c] = Wout[(size_t)(kk + k) * GFD + c];
        }
        __syncthreads();
        #pragma unroll
        for (int k = 0; k < 32; k++) {
            float av[4], bv[4];
            #pragma unroll
            for (int i = 0; i < 4; i++) av[i] = As[ty * 4 + i][k];
            #pragma unroll
            for (int j = 0; j < 4; j++) bv[j] = Bs[k][tx * 4 + j];
            #pragma unroll
            for (int i = 0; i < 4; i++)
                #pragma unroll
                for (int j = 0; j < 4; j++) acc[i][j] += av[i] * bv[j];
        }
        __syncthreads();
    }
    #pragma unroll
    for (int i = 0; i < 4; i++) {
        int grow = rBase + ty * 4 + i;
        #pragma unroll
        for (int j = 0; j < 4; j++) {
            int col = tx * 4 + j;
            out[(size_t)grow * GFD + col] =
                acc[i][j] + b_out[col] + feat[(size_t)grow * GFD + col];
        }
    }
}

// ---------------------------------------------------------------------------
// Launch
// ---------------------------------------------------------------------------
extern "C" void kernel_launch(void* const* d_in, const int* in_sizes, int n_in,
                              void* d_out, int out_size)
{
    const float* means      = (const float*)d_in[0];
    const float* scales     = (const float*)d_in[1];
    const float* rotations  = (const float*)d_in[2];
    const float* features   = (const float*)d_in[3];
    const float* transforms = (const float*)d_in[4];
    const float* projection = (const float*)d_in[5];
    const float* image_feat = (const float*)d_in[6];
    const float* Wq         = (const float*)d_in[7];
    const float* Wk         = (const float*)d_in[8];
    const float* Wv         = (const float*)d_in[9];
    const float* W_off      = (const float*)d_in[10];
    const float* b_off      = (const float*)d_in[11];
    const float* Wout       = (const float*)d_in[12];
    const float* b_out      = (const float*)d_in[13];
    float* out = (float*)d_out;

    // 1) KV feature maps: [1024 x 4096] GEMM, written pixel-major fp16
    kv_gemm<<<dim3(NPIX / 64, 1024 / 128), 256>>>(Wk, Wv, image_feat);
    // 2) Q projection: [24576 x 512]
    q_gemm<<<dim3(ATTN / 64, NROW / 64), 256>>>(features, Wq);
    // 3a) offsets -> sample coordinates
    coord_kernel<<<NG, 256>>>(means, scales, rotations, transforms,
                              projection, W_off, b_off);
    // 3b) barrier-free gather + attention (one warp per (g,h))
    gather_attn<<<NG, 256>>>();
    // 4) output projection + bias + residual
    out_gemm<<<NROW / 128, 256>>>(Wout, b_out, features, out);
}

// round 10
// speedup vs baseline: 1.2791x; 1.0452x over previous
#include <cuda_runtime.h>
#include <cuda_fp16.h>
#include <math.h>

// ---------------------------------------------------------------------------
// Problem constants
//   G=8192 gaussians, BS=1, 3 tokens, GFD=32, ATTN=512, H=8 heads, HD=64
//   image_features [256,64,64], K = 12 sample points (6 fixed + 6 learned)
// ---------------------------------------------------------------------------
#define NG      8192
#define NROW    (NG*3)        // 24576 (gaussian,token) rows
#define ATTN    512
#define GFD     32
#define NHEAD   8
#define HDIM    64
#define IMGW    64
#define IMGH    64
#define NPIX    (IMGW*IMGH)   // 4096
#define CIMG    256
#define NK      12

// Scratch (static device globals: allocation-free per harness rules)
// g_kvh layout: per pixel, 256 channel-pairs; slot 2p = K half2 (ch 2p,2p+1),
//               slot 2p+1 = V half2.  One 8-byte load fetches K+V for a lane.
__device__ __half2 g_kvh[NPIX * 512];      // 8 MB, L2-resident
__device__ float   g_q[NROW * ATTN];       // q_full                       (50 MB)
__device__ float   g_attn[NROW * ATTN];    // attention output             (50 MB)
__device__ float2  g_samp[NG * NHEAD * NK];// sample coords (x,y) per (g,h,k) (6 MB)

__constant__ float c_fix[6][3] = {
    {0.f,0.f,0.f},{1.f,0.f,0.f},{0.f,1.f,0.f},
    {0.f,0.f,1.f},{-1.f,0.f,0.f},{0.f,-1.f,0.f}};

__device__ __forceinline__ float sigm_clamped(float x) {
    x = fminf(fmaxf(x, -9.21f), 9.21f);
    return 1.0f / (1.0f + __expf(-x));
}

// 5-stage butterfly warp sum (redux.sync.f32 is not available on sm_103 target)
__device__ __forceinline__ float warp_sum(float v) {
    #pragma unroll
    for (int o = 16; o > 0; o >>= 1) v += __shfl_xor_sync(0xffffffffu, v, o);
    return v;
}

// ---------------------------------------------------------------------------
// Kernel 1: KV maps.  C[a,pix] = sum_c Wkv[a,c] * img[c,pix]
//   a in [0,1024): rows 0..511 from Wk, 512..1023 from Wv.
//   Written transposed + fp16-packed + K/V-interleaved into g_kvh.
// ---------------------------------------------------------------------------
__global__ void __launch_bounds__(256) kv_gemm(
    const float* __restrict__ Wk, const float* __restrict__ Wv,
    const float* __restrict__ img)
{
    __shared__ float As[128][17];   // a x k (padded)
    __shared__ float Bs[16][64];    // k x pix

    const int aBase = blockIdx.y * 128;
    const int pBase = blockIdx.x * 64;
    const int tid = threadIdx.x;
    const int tx = tid & 15;        // pix group (x4)
    const int ty = tid >> 4;        // a group (x8)

    float acc[8][4] = {};

    for (int kk = 0; kk < CIMG; kk += 16) {
        #pragma unroll
        for (int i = tid; i < 128 * 16; i += 256) {
            int a = i >> 4, k = i & 15;
            int ga = aBase + a;
            float v = (ga < 512) ? Wk[ga * CIMG + kk + k]
                                 : Wv[(ga - 512) * CIMG + kk + k];
            As[a][k] = v;
        }
        #pragma unroll
        for (int i = tid; i < 16 * 64; i += 256) {
            int k = i >> 6, p = i & 63;
            Bs[k][p] = img[(kk + k) * NPIX + pBase + p];
        }
        __syncthreads();
        #pragma unroll
        for (int k = 0; k < 16; k++) {
            float av[8], bv[4];
            #pragma unroll
            for (int i = 0; i < 8; i++) av[i] = As[ty * 8 + i][k];
            #pragma unroll
            for (int j = 0; j < 4; j++) bv[j] = Bs[k][tx * 4 + j];
            #pragma unroll
            for (int i = 0; i < 8; i++)
                #pragma unroll
                for (int j = 0; j < 4; j++) acc[i][j] += av[i] * bv[j];
        }
        __syncthreads();
    }
    // Epilogue: pack to half2, interleaved K/V slots.
    const int paBase = (aBase >> 1) + ty * 4;   // global channel-pair index (0..511)
    #pragma unroll
    for (int j = 0; j < 4; j++) {
        int pix = pBase + tx * 4 + j;
        #pragma unroll
        for (int p = 0; p < 4; p++) {
            int pa = paBase + p;
            int slot = (pa < 256) ? (2 * pa) : (2 * (pa - 256) + 1);
            g_kvh[(size_t)pix * 512 + slot] =
                __floats2half2_rn(acc[2 * p][j], acc[2 * p + 1][j]);
        }
    }
}

// ---------------------------------------------------------------------------
// Kernel 2: Q projection.  g_q[row, a] = sum_f feat[row, f] * Wq[f, a]
// ---------------------------------------------------------------------------
__global__ void __launch_bounds__(256) q_gemm(
    const float* __restrict__ feat, const float* __restrict__ Wq)
{
    __shared__ float As[64][33];   // rows x k
    __shared__ float Bs[32][64];   // k x cols

    const int rBase = blockIdx.y * 64;
    const int cBase = blockIdx.x * 64;
    const int tid = threadIdx.x;
    const int tx = tid & 15, ty = tid >> 4;

    #pragma unroll
    for (int i = tid; i < 64 * 32; i += 256) {
        int r = i >> 5, k = i & 31;
        As[r][k] = feat[(size_t)(rBase + r) * 32 + k];
    }
    #pragma unroll
    for (int i = tid; i < 32 * 64; i += 256) {
        int k = i >> 6, c = i & 63;
        Bs[k][c] = Wq[(size_t)k * ATTN + cBase + c];
    }
    __syncthreads();

    float acc[4][4] = {};
    #pragma unroll
    for (int k = 0; k < 32; k++) {
        float av[4], bv[4];
        #pragma unroll
        for (int i = 0; i < 4; i++) av[i] = As[ty * 4 + i][k];
        #pragma unroll
        for (int j = 0; j < 4; j++) bv[j] = Bs[k][tx * 4 + j];
        #pragma unroll
        for (int i = 0; i < 4; i++)
            #pragma unroll
            for (int j = 0; j < 4; j++) acc[i][j] += av[i] * bv[j];
    }
    #pragma unroll
    for (int i = 0; i < 4; i++)
        #pragma unroll
        for (int j = 0; j < 4; j++)
            g_q[(size_t)(rBase + ty * 4 + i) * ATTN + cBase + tx * 4 + j] = acc[i][j];
}

// ---------------------------------------------------------------------------
// Kernel 3a: coordinate precompute.
//   One block per gaussian, one warp per head. Computes OffsetNet logits and
//   the 12 continuous sample coords (x,y) per (g,h), stored to g_samp.
// ---------------------------------------------------------------------------
__global__ void __launch_bounds__(256) coord_kernel(
    const float* __restrict__ means, const float* __restrict__ scales,
    const float* __restrict__ rots, const float* __restrict__ transforms,
    const float* __restrict__ proj, const float* __restrict__ W_off,
    const float* __restrict__ b_off)
{
    const int g = blockIdx.x;
    const int tid = threadIdx.x;
    const int h = tid >> 5;
    const int lane = tid & 31;

    __shared__ float sqm[NHEAD][HDIM];   // per-head token-mean query
    __shared__ float slog[NHEAD][18];    // offset logits
    __shared__ float sW[67 * 18];
    __shared__ float sb[18];
    __shared__ float sP[12];
    __shared__ float sMisc[16];          // 0-2 mean_w, 3-11 R(row major), 12-14 scales

    for (int i = tid; i < 67 * 18; i += 256) sW[i] = W_off[i];
    if (tid < 18) sb[tid] = b_off[tid];
    if (tid >= 32 && tid < 44) sP[tid - 32] = proj[tid - 32];
    if (tid == 64) {
        float mx = means[g * 3], my = means[g * 3 + 1], mz = means[g * 3 + 2];
        const float* T = transforms + (size_t)g * 16;
        sMisc[0] = T[0] * mx + T[1] * my + T[2]  * mz + T[3];
        sMisc[1] = T[4] * mx + T[5] * my + T[6]  * mz + T[7];
        sMisc[2] = T[8] * mx + T[9] * my + T[10] * mz + T[11];
        float qw = rots[g * 4], qx = rots[g * 4 + 1], qy = rots[g * 4 + 2], qz = rots[g * 4 + 3];
        float inv = rsqrtf(qw * qw + qx * qx + qy * qy + qz * qz);
        qw *= inv; qx *= inv; qy *= inv; qz *= inv;
        sMisc[3]  = 1.f - 2.f * (qy * qy + qz * qz);
        sMisc[4]  = 2.f * (qx * qy - qw * qz);
        sMisc[5]  = 2.f * (qx * qz + qw * qy);
        sMisc[6]  = 2.f * (qx * qy + qw * qz);
        sMisc[7]  = 1.f - 2.f * (qx * qx + qz * qz);
        sMisc[8]  = 2.f * (qy * qz - qw * qx);
        sMisc[9]  = 2.f * (qx * qz - qw * qy);
        sMisc[10] = 2.f * (qy * qz + qw * qx);
        sMisc[11] = 1.f - 2.f * (qx * qx + qy * qy);
        sMisc[12] = scales[g * 3]; sMisc[13] = scales[g * 3 + 1]; sMisc[14] = scales[g * 3 + 2];
    }

    // per-head token-mean query (2 channels per lane, straight from g_q)
    {
        const float* qg = g_q + (size_t)g * 3 * ATTN + h * HDIM + lane * 2;
        float2 q0 = *(const float2*)(qg);
        float2 q1 = *(const float2*)(qg + ATTN);
        float2 q2 = *(const float2*)(qg + 2 * ATTN);
        sqm[h][lane * 2]     = (q0.x + q1.x + q2.x) * (1.0f / 3.0f);
        sqm[h][lane * 2 + 1] = (q0.y + q1.y + q2.y) * (1.0f / 3.0f);
    }
    __syncthreads();

    // offset logits: off_in = [mean_w(3), q_mean(64)] @ W_off + b_off
    if (lane < 18) {
        float acc = sb[lane] + sMisc[0] * sW[lane] + sMisc[1] * sW[18 + lane] + sMisc[2] * sW[36 + lane];
        #pragma unroll 8
        for (int c = 0; c < HDIM; c++) acc += sqm[h][c] * sW[(3 + c) * 18 + lane];
        slog[h][lane] = acc;
    }
    __syncwarp();

    if (lane < NK) {
        const int k = lane;
        float s0, s1, s2;
        if (k < 6) {
            s0 = c_fix[k][0]; s1 = c_fix[k][1]; s2 = c_fix[k][2];
        } else {
            int b = (k - 6) * 3;
            s0 = sigm_clamped(slog[h][b])     - 0.5f;
            s1 = sigm_clamped(slog[h][b + 1]) - 0.5f;
            s2 = sigm_clamped(slog[h][b + 2]) - 0.5f;
        }
        float o0 = s0 * sMisc[12], o1 = s1 * sMisc[13], o2 = s2 * sMisc[14];
        // world offset = R^T @ o + mean_w
        float wx = sMisc[3] * o0 + sMisc[6] * o1 + sMisc[9]  * o2 + sMisc[0];
        float wy = sMisc[4] * o0 + sMisc[7] * o1 + sMisc[10] * o2 + sMisc[1];
        float wz = sMisc[5] * o0 + sMisc[8] * o1 + sMisc[11] * o2 + sMisc[2];
        float p0 = sP[0] * wx + sP[1] * wy + sP[2]  * wz + sP[3];
        float p1 = sP[4] * wx + sP[5] * wy + sP[6]  * wz + sP[7];
        float p2 = sP[8] * wx + sP[9] * wy + sP[10] * wz + sP[11];
        float z = fmaxf(p2, 1e-5f);
        float xn = fminf(fmaxf(p0 / z * (1.0f / IMGW), 0.0f), 0.9999f);
        float yn = fminf(fmaxf(p1 / z * (1.0f / IMGH), 0.0f), 0.9999f);
        float2 xy;
        xy.x = xn * (float)IMGW - 0.5f;
        xy.y = yn * (float)IMGH - 0.5f;
        g_samp[((size_t)g * NHEAD + h) * NK + k] = xy;
    }
}

// ---------------------------------------------------------------------------
// Kernel 3b: gather + attention.  ONE WARP per (gaussian, head).
//   No shared memory, no block barriers.  Butterfly warp reductions, fast
//   exp (MUFU), fused 8-byte K+V gather loads.
// ---------------------------------------------------------------------------
__global__ void __launch_bounds__(256) gather_attn()
{
    const int wid  = (blockIdx.x * 256 + threadIdx.x) >> 5;  // 0..65535
    const int lane = threadIdx.x & 31;
    const int g = wid >> 3;
    const int h = wid & 7;
    const int hidx = h * 32 + lane;            // channel-pair index (0..255)

    const float2* __restrict__ cp = g_samp + (size_t)wid * NK;

    float ksA[NK], ksB[NK], vsA[NK], vsB[NK];

    #pragma unroll
    for (int k = 0; k < NK; k++) {
        float2 xy = cp[k];                      // uniform within warp -> broadcast
        float xf = floorf(xy.x), yf = floorf(xy.y);
        int x0 = (int)xf, y0 = (int)yf;
        float fx = xy.x - xf, fy = xy.y - yf;
        float w00 = (1.f - fx) * (1.f - fy), w10 = fx * (1.f - fy);
        float w01 = (1.f - fx) * fy,         w11 = fx * fy;

        float ka = 0.f, kb = 0.f, va = 0.f, vb = 0.f;
        #pragma unroll
        for (int c = 0; c < 4; c++) {
            int cx = x0 + (c & 1), cy = y0 + (c >> 1);
            float w = (c == 0) ? w00 : (c == 1) ? w10 : (c == 2) ? w01 : w11;
            if (cx >= 0 && cx < IMGW && cy >= 0 && cy < IMGH) {
                // one 8-byte load: K half2 + V half2
                const float2 raw = *(const float2*)(g_kvh + (size_t)(cy * IMGW + cx) * 512 + 2 * hidx);
                float2 kf = __half22float2(*(const __half2*)&raw.x);
                float2 vf = __half22float2(*(const __half2*)&raw.y);
                ka += w * kf.x; kb += w * kf.y;
                va += w * vf.x; vb += w * vf.y;
            }
        }
        ksA[k] = ka; ksB[k] = kb; vsA[k] = va; vsB[k] = vb;
    }

    const float* qg = g_q + (size_t)g * 3 * ATTN + h * HDIM + lane * 2;

    #pragma unroll
    for (int t = 0; t < 3; t++) {
        float2 q = *(const float2*)(qg + t * ATTN);
        float sc[NK];
        #pragma unroll
        for (int k = 0; k < NK; k++)
            sc[k] = warp_sum(q.x * ksA[k] + q.y * ksB[k]) * 0.125f;   // HD^-0.5 = 1/8
        float m = sc[0];
        #pragma unroll
        for (int k = 1; k < NK; k++) m = fmaxf(m, sc[k]);
        float e[NK], sum = 0.f;
        #pragma unroll
        for (int k = 0; k < NK; k++) { e[k] = __expf(sc[k] - m); sum += e[k]; }
        float inv = __fdividef(1.0f, sum);
        float oa = 0.f, ob = 0.f;
        #pragma unroll
        for (int k = 0; k < NK; k++) {
            float a = e[k] * inv;
            oa += a * vsA[k]; ob += a * vsB[k];
        }
        float2 o2v; o2v.x = oa; o2v.y = ob;
        *(float2*)(g_attn + (size_t)(g * 3 + t) * ATTN + h * HDIM + lane * 2) = o2v;
    }
}

// ---------------------------------------------------------------------------
// Kernel 4: output projection + residual.
//   out[row, f] = sum_a g_attn[row, a] * Wout[a, f] + b_out[f] + feat[row, f]
// ---------------------------------------------------------------------------
__global__ void __launch_bounds__(256) out_gemm(
    const float* __restrict__ Wout, const float* __restrict__ b_out,
    const float* __restrict__ feat, float* __restrict__ out)
{
    __shared__ float As[128][33];  // rows x kchunk (padded)
    __shared__ float Bs[32][33];   // k x col (padded)

    const int rBase = blockIdx.x * 128;
    const int tid = threadIdx.x;
    const int tx = tid & 7;        // col group (x4) -> 32 cols
    const int ty = tid >> 3;       // row group (x4) -> 128 rows

    float acc[4][4] = {};

    for (int kk = 0; kk < ATTN; kk += 32) {
        #pragma unroll
        for (int i = tid; i < 128 * 32; i += 256) {
            int r = i >> 5, k = i & 31;
            As[r][k] = g_attn[(size_t)(rBase + r) * ATTN + kk + k];
        }
        #pragma unroll
        for (int i = tid; i < 32 * 32; i += 256) {
            int k = i >> 5, c = i & 31;
            Bs[k][c] = Wout[(size_t)(kk + k) * GFD + c];
        }
        __syncthreads();
        #pragma unroll
        for (int k = 0; k < 32; k++) {
            float av[4], bv[4];
            #pragma unroll
            for (int i = 0; i < 4; i++) av[i] = As[ty * 4 + i][k];
            #pragma unroll
            for (int j = 0; j < 4; j++) bv[j] = Bs[k][tx * 4 + j];
            #pragma unroll
            for (int i = 0; i < 4; i++)
                #pragma unroll
                for (int j = 0; j < 4; j++) acc[i][j] += av[i] * bv[j];
        }
        __syncthreads();
    }
    #pragma unroll
    for (int i = 0; i < 4; i++) {
        int grow = rBase + ty * 4 + i;
        #pragma unroll
        for (int j = 0; j < 4; j++) {
            int col = tx * 4 + j;
            out[(size_t)grow * GFD + col] =
                acc[i][j] + b_out[col] + feat[(size_t)grow * GFD + col];
        }
    }
}

// ---------------------------------------------------------------------------
// Launch
// ---------------------------------------------------------------------------
extern "C" void kernel_launch(void* const* d_in, const int* in_sizes, int n_in,
                              void* d_out, int out_size)
{
    const float* means      = (const float*)d_in[0];
    const float* scales     = (const float*)d_in[1];
    const float* rotations  = (const float*)d_in[2];
    const float* features   = (const float*)d_in[3];
    const float* transforms = (const float*)d_in[4];
    const float* projection = (const float*)d_in[5];
    const float* image_feat = (const float*)d_in[6];
    const float* Wq         = (const float*)d_in[7];
    const float* Wk         = (const float*)d_in[8];
    const float* Wv         = (const float*)d_in[9];
    const float* W_off      = (const float*)d_in[10];
    const float* b_off      = (const float*)d_in[11];
    const float* Wout       = (const float*)d_in[12];
    const float* b_out      = (const float*)d_in[13];
    float* out = (float*)d_out;

    // 1) KV feature maps: [1024 x 4096] GEMM, written pixel-major fp16 interleaved
    kv_gemm<<<dim3(NPIX / 64, 1024 / 128), 256>>>(Wk, Wv, image_feat);
    // 2) Q projection: [24576 x 512]
    q_gemm<<<dim3(ATTN / 64, NROW / 64), 256>>>(features, Wq);
    // 3a) offsets -> sample coordinates
    coord_kernel<<<NG, 256>>>(means, scales, rotations, transforms,
                              projection, W_off, b_off);
    // 3b) barrier-free gather + attention (one warp per (g,h))
    gather_attn<<<NG, 256>>>();
    // 4) output projection + bias + residual
    out_gemm<<<NROW / 128, 256>>>(Wout, b_out, features, out);
}

// round 11
// speedup vs baseline: 1.4100x; 1.1024x over previous
#include <cuda_runtime.h>
#include <cuda_fp16.h>
#include <math.h>

// ---------------------------------------------------------------------------
// Problem constants
//   G=8192 gaussians, BS=1, 3 tokens, GFD=32, ATTN=512, H=8 heads, HD=64
//   image_features [256,64,64], K = 12 sample points (6 fixed + 6 learned)
// ---------------------------------------------------------------------------
#define NG      8192
#define NROW    (NG*3)        // 24576 (gaussian,token) rows
#define ATTN    512
#define GFD     32
#define NHEAD   8
#define HDIM    64
#define IMGW    64
#define IMGH    64
#define NPIX    (IMGW*IMGH)   // 4096
#define CIMG    256
#define NK      12

// Scratch (static device globals: allocation-free per harness rules)
// g_kvh layout: per pixel, 256 channel-pairs; slot 2p = K half2 (ch 2p,2p+1),
//               slot 2p+1 = V half2.  One 8-byte load fetches K+V for a lane.
__device__ __half2 g_kvh[NPIX * 512];       // 8 MB, L2-resident
__device__ float   g_q[NROW * ATTN];        // q_full                       (50 MB)
__device__ float   g_attn[NROW * ATTN];     // attention output             (50 MB)
__device__ float4  g_w4[NG * NHEAD * NK];   // bilinear corner weights      (12.6 MB)
__device__ int4    g_o4[NG * NHEAD * NK];   // clamped corner offsets (x512)(12.6 MB)

__constant__ float c_fix[6][3] = {
    {0.f,0.f,0.f},{1.f,0.f,0.f},{0.f,1.f,0.f},
    {0.f,0.f,1.f},{-1.f,0.f,0.f},{0.f,-1.f,0.f}};

__device__ __forceinline__ float sigm_clamped(float x) {
    x = fminf(fmaxf(x, -9.21f), 9.21f);
    return 1.0f / (1.0f + __expf(-x));
}

// 5-stage butterfly warp sum (redux.sync.f32 not available on sm_103 target)
__device__ __forceinline__ float warp_sum(float v) {
    #pragma unroll
    for (int o = 16; o > 0; o >>= 1) v += __shfl_xor_sync(0xffffffffu, v, o);
    return v;
}

// ---------------------------------------------------------------------------
// Kernel 1: KV maps.  C[a,pix] = sum_c Wkv[a,c] * img[c,pix]
//   a in [0,1024): rows 0..511 from Wk, 512..1023 from Wv.
//   Block tile 128(a) x 128(pix), thread tile 8x8, k-major smem (LDS.128).
//   Written transposed + fp16-packed + K/V-interleaved into g_kvh.
// ---------------------------------------------------------------------------
__global__ void __launch_bounds__(256) kv_gemm(
    const float* __restrict__ Wk, const float* __restrict__ Wv,
    const float* __restrict__ img)
{
    __shared__ float As[16][132];   // k x a (padded)
    __shared__ float Bs[16][132];   // k x pix (padded)

    const int aBase = blockIdx.y * 128;
    const int pBase = blockIdx.x * 128;
    const int tid = threadIdx.x;
    const int tx = tid & 15;        // pix group (x8)
    const int ty = tid >> 4;        // a group (x8)

    float acc[8][8] = {};

    for (int kk = 0; kk < CIMG; kk += 16) {
        // As: k fastest in gmem read (coalesced 16-float rows), k-major smem
        #pragma unroll
        for (int i = tid; i < 128 * 16; i += 256) {
            int a = i >> 4, k = i & 15;
            int ga = aBase + a;
            float v = (ga < 512) ? Wk[ga * CIMG + kk + k]
                                 : Wv[(ga - 512) * CIMG + kk + k];
            As[k][a] = v;
        }
        // Bs: pix fastest (coalesced 128-float rows)
        #pragma unroll
        for (int i = tid; i < 16 * 128; i += 256) {
            int k = i >> 7, p = i & 127;
            Bs[k][p] = img[(kk + k) * NPIX + pBase + p];
        }
        __syncthreads();
        #pragma unroll
        for (int k = 0; k < 16; k++) {
            float av[8], bv[8];
            #pragma unroll
            for (int i = 0; i < 8; i++) av[i] = As[k][ty * 8 + i];
            #pragma unroll
            for (int j = 0; j < 8; j++) bv[j] = Bs[k][tx * 8 + j];
            #pragma unroll
            for (int i = 0; i < 8; i++)
                #pragma unroll
                for (int j = 0; j < 8; j++) acc[i][j] += av[i] * bv[j];
        }
        __syncthreads();
    }
    // Epilogue: pack to half2, interleaved K/V slots.
    const int paBase = (aBase >> 1) + ty * 4;   // global channel-pair index
    #pragma unroll
    for (int j = 0; j < 8; j++) {
        int pix = pBase + tx * 8 + j;
        #pragma unroll
        for (int p = 0; p < 4; p++) {
            int pa = paBase + p;
            int slot = (pa < 256) ? (2 * pa) : (2 * (pa - 256) + 1);
            g_kvh[(size_t)pix * 512 + slot] =
                __floats2half2_rn(acc[2 * p][j], acc[2 * p + 1][j]);
        }
    }
}

// ---------------------------------------------------------------------------
// Kernel 2: Q projection.  g_q[row, a] = sum_f feat[row, f] * Wq[f, a]
// ---------------------------------------------------------------------------
__global__ void __launch_bounds__(256) q_gemm(
    const float* __restrict__ feat, const float* __restrict__ Wq)
{
    __shared__ float As[64][33];   // rows x k
    __shared__ float Bs[32][64];   // k x cols

    const int rBase = blockIdx.y * 64;
    const int cBase = blockIdx.x * 64;
    const int tid = threadIdx.x;
    const int tx = tid & 15, ty = tid >> 4;

    #pragma unroll
    for (int i = tid; i < 64 * 32; i += 256) {
        int r = i >> 5, k = i & 31;
        As[r][k] = feat[(size_t)(rBase + r) * 32 + k];
    }
    #pragma unroll
    for (int i = tid; i < 32 * 64; i += 256) {
        int k = i >> 6, c = i & 63;
        Bs[k][c] = Wq[(size_t)k * ATTN + cBase + c];
    }
    __syncthreads();

    float acc[4][4] = {};
    #pragma unroll
    for (int k = 0; k < 32; k++) {
        float av[4], bv[4];
        #pragma unroll
        for (int i = 0; i < 4; i++) av[i] = As[ty * 4 + i][k];
        #pragma unroll
        for (int j = 0; j < 4; j++) bv[j] = Bs[k][tx * 4 + j];
        #pragma unroll
        for (int i = 0; i < 4; i++)
            #pragma unroll
            for (int j = 0; j < 4; j++) acc[i][j] += av[i] * bv[j];
    }
    #pragma unroll
    for (int i = 0; i < 4; i++)
        #pragma unroll
        for (int j = 0; j < 4; j++)
            g_q[(size_t)(rBase + ty * 4 + i) * ATTN + cBase + tx * 4 + j] = acc[i][j];
}

// ---------------------------------------------------------------------------
// Kernel 3a: coordinate precompute.
//   One block per gaussian, one warp per head. Computes OffsetNet logits, the
//   12 sample points, and the fully-resolved bilinear weights + clamped
//   corner offsets (so gather_attn does zero coordinate math).
// ---------------------------------------------------------------------------
__global__ void __launch_bounds__(256) coord_kernel(
    const float* __restrict__ means, const float* __restrict__ scales,
    const float* __restrict__ rots, const float* __restrict__ transforms,
    const float* __restrict__ proj, const float* __restrict__ W_off,
    const float* __restrict__ b_off)
{
    const int g = blockIdx.x;
    const int tid = threadIdx.x;
    const int h = tid >> 5;
    const int lane = tid & 31;

    __shared__ float sqm[NHEAD][HDIM];   // per-head token-mean query
    __shared__ float slog[NHEAD][18];    // offset logits
    __shared__ float sW[67 * 18];
    __shared__ float sb[18];
    __shared__ float sP[12];
    __shared__ float sMisc[16];          // 0-2 mean_w, 3-11 R(row major), 12-14 scales

    for (int i = tid; i < 67 * 18; i += 256) sW[i] = W_off[i];
    if (tid < 18) sb[tid] = b_off[tid];
    if (tid >= 32 && tid < 44) sP[tid - 32] = proj[tid - 32];
    if (tid == 64) {
        float mx = means[g * 3], my = means[g * 3 + 1], mz = means[g * 3 + 2];
        const float* T = transforms + (size_t)g * 16;
        sMisc[0] = T[0] * mx + T[1] * my + T[2]  * mz + T[3];
        sMisc[1] = T[4] * mx + T[5] * my + T[6]  * mz + T[7];
        sMisc[2] = T[8] * mx + T[9] * my + T[10] * mz + T[11];
        float qw = rots[g * 4], qx = rots[g * 4 + 1], qy = rots[g * 4 + 2], qz = rots[g * 4 + 3];
        float inv = rsqrtf(qw * qw + qx * qx + qy * qy + qz * qz);
        qw *= inv; qx *= inv; qy *= inv; qz *= inv;
        sMisc[3]  = 1.f - 2.f * (qy * qy + qz * qz);
        sMisc[4]  = 2.f * (qx * qy - qw * qz);
        sMisc[5]  = 2.f * (qx * qz + qw * qy);
        sMisc[6]  = 2.f * (qx * qy + qw * qz);
        sMisc[7]  = 1.f - 2.f * (qx * qx + qz * qz);
        sMisc[8]  = 2.f * (qy * qz - qw * qx);
        sMisc[9]  = 2.f * (qx * qz - qw * qy);
        sMisc[10] = 2.f * (qy * qz + qw * qx);
        sMisc[11] = 1.f - 2.f * (qx * qx + qy * qy);
        sMisc[12] = scales[g * 3]; sMisc[13] = scales[g * 3 + 1]; sMisc[14] = scales[g * 3 + 2];
    }

    // per-head token-mean query (2 channels per lane, straight from g_q)
    {
        const float* qg = g_q + (size_t)g * 3 * ATTN + h * HDIM + lane * 2;
        float2 q0 = *(const float2*)(qg);
        float2 q1 = *(const float2*)(qg + ATTN);
        float2 q2 = *(const float2*)(qg + 2 * ATTN);
        sqm[h][lane * 2]     = (q0.x + q1.x + q2.x) * (1.0f / 3.0f);
        sqm[h][lane * 2 + 1] = (q0.y + q1.y + q2.y) * (1.0f / 3.0f);
    }
    __syncthreads();

    // offset logits: off_in = [mean_w(3), q_mean(64)] @ W_off + b_off
    if (lane < 18) {
        float acc = sb[lane] + sMisc[0] * sW[lane] + sMisc[1] * sW[18 + lane] + sMisc[2] * sW[36 + lane];
        #pragma unroll 8
        for (int c = 0; c < HDIM; c++) acc += sqm[h][c] * sW[(3 + c) * 18 + lane];
        slog[h][lane] = acc;
    }
    __syncwarp();

    if (lane < NK) {
        const int k = lane;
        float s0, s1, s2;
        if (k < 6) {
            s0 = c_fix[k][0]; s1 = c_fix[k][1]; s2 = c_fix[k][2];
        } else {
            int b = (k - 6) * 3;
            s0 = sigm_clamped(slog[h][b])     - 0.5f;
            s1 = sigm_clamped(slog[h][b + 1]) - 0.5f;
            s2 = sigm_clamped(slog[h][b + 2]) - 0.5f;
        }
        float o0 = s0 * sMisc[12], o1 = s1 * sMisc[13], o2 = s2 * sMisc[14];
        // world offset = R^T @ o + mean_w
        float wx = sMisc[3] * o0 + sMisc[6] * o1 + sMisc[9]  * o2 + sMisc[0];
        float wy = sMisc[4] * o0 + sMisc[7] * o1 + sMisc[10] * o2 + sMisc[1];
        float wz = sMisc[5] * o0 + sMisc[8] * o1 + sMisc[11] * o2 + sMisc[2];
        float p0 = sP[0] * wx + sP[1] * wy + sP[2]  * wz + sP[3];
        float p1 = sP[4] * wx + sP[5] * wy + sP[6]  * wz + sP[7];
        float p2 = sP[8] * wx + sP[9] * wy + sP[10] * wz + sP[11];
        float z = fmaxf(p2, 1e-5f);
        float xn = fminf(fmaxf(p0 / z * (1.0f / IMGW), 0.0f), 0.9999f);
        float yn = fminf(fmaxf(p1 / z * (1.0f / IMGH), 0.0f), 0.9999f);
        float x = xn * (float)IMGW - 0.5f;
        float y = yn * (float)IMGH - 0.5f;

        // Fully resolve bilinear sampling: weights (zeroed when OOB) + clamped
        // corner offsets in units of half2 (pixel * 512).
        float xf = floorf(x), yf = floorf(y);
        int x0 = (int)xf, y0 = (int)yf;
        float fx = x - xf, fy = y - yf;
        float w00 = (1.f - fx) * (1.f - fy), w10 = fx * (1.f - fy);
        float w01 = (1.f - fx) * fy,         w11 = fx * fy;
        int x1 = x0 + 1, y1 = y0 + 1;
        float vx0 = (x0 >= 0) ? 1.f : 0.f;   // x0 <= 63 always (x <= 63.494)
        float vx1 = (x1 <= IMGW - 1) ? 1.f : 0.f;
        float vy0 = (y0 >= 0) ? 1.f : 0.f;
        float vy1 = (y1 <= IMGH - 1) ? 1.f : 0.f;
        int cx0 = max(x0, 0), cx1 = min(x1, IMGW - 1);
        int cy0 = max(y0, 0), cy1 = min(y1, IMGH - 1);

        size_t idx = ((size_t)g * NHEAD + h) * NK + k;
        float4 w4;
        w4.x = w00 * vx0 * vy0;
        w4.y = w10 * vx1 * vy0;
        w4.z = w01 * vx0 * vy1;
        w4.w = w11 * vx1 * vy1;
        g_w4[idx] = w4;
        int4 o4;
        o4.x = (cy0 * IMGW + cx0) * 512;
        o4.y = (cy0 * IMGW + cx1) * 512;
        o4.z = (cy1 * IMGW + cx0) * 512;
        o4.w = (cy1 * IMGW + cx1) * 512;
        g_o4[idx] = o4;
    }
}

// ---------------------------------------------------------------------------
// Kernel 3b: gather + attention.  ONE WARP per (gaussian, head).
//   No smem, no barriers, no coordinate math: per sample point, 2 uniform
//   vector loads give weights + offsets; 4 fused 8-byte K+V gathers; butterfly
//   score reduction; max-free softmax (scores are O(5), fp32 exp is exact).
// ---------------------------------------------------------------------------
__global__ void __launch_bounds__(256) gather_attn()
{
    const int wid  = (blockIdx.x * 256 + threadIdx.x) >> 5;  // 0..65535
    const int lane = threadIdx.x & 31;
    const int g = wid >> 3;
    const int h = wid & 7;
    const int hidx2 = 2 * (h * 32 + lane);     // half2 offset within pixel record

    const float4* __restrict__ wp = g_w4 + (size_t)wid * NK;
    const int4*   __restrict__ op = g_o4 + (size_t)wid * NK;

    float ksA[NK], ksB[NK], vsA[NK], vsB[NK];

    #pragma unroll
    for (int k = 0; k < NK; k++) {
        float4 w = wp[k];                       // warp-uniform broadcast loads
        int4   o = op[k];
        float ka, kb, va, vb;
        {
            const float2 raw = *(const float2*)(g_kvh + o.x + hidx2);
            float2 kf = __half22float2(*(const __half2*)&raw.x);
            float2 vf = __half22float2(*(const __half2*)&raw.y);
            ka = w.x * kf.x; kb = w.x * kf.y; va = w.x * vf.x; vb = w.x * vf.y;
        }
        {
            const float2 raw = *(const float2*)(g_kvh + o.y + hidx2);
            float2 kf = __half22float2(*(const __half2*)&raw.x);
            float2 vf = __half22float2(*(const __half2*)&raw.y);
            ka += w.y * kf.x; kb += w.y * kf.y; va += w.y * vf.x; vb += w.y * vf.y;
        }
        {
            const float2 raw = *(const float2*)(g_kvh + o.z + hidx2);
            float2 kf = __half22float2(*(const __half2*)&raw.x);
            float2 vf = __half22float2(*(const __half2*)&raw.y);
            ka += w.z * kf.x; kb += w.z * kf.y; va += w.z * vf.x; vb += w.z * vf.y;
        }
        {
            const float2 raw = *(const float2*)(g_kvh + o.w + hidx2);
            float2 kf = __half22float2(*(const __half2*)&raw.x);
            float2 vf = __half22float2(*(const __half2*)&raw.y);
            ka += w.w * kf.x; kb += w.w * kf.y; va += w.w * vf.x; vb += w.w * vf.y;
        }
        ksA[k] = ka; ksB[k] = kb; vsA[k] = va; vsB[k] = vb;
    }

    const float* qg = g_q + (size_t)g * 3 * ATTN + h * HDIM + lane * 2;

    #pragma unroll
    for (int t = 0; t < 3; t++) {
        float2 q = *(const float2*)(qg + t * ATTN);
        q.x *= 0.125f; q.y *= 0.125f;          // fold HD^-0.5 into q
        float e[NK], sum = 0.f;
        #pragma unroll
        for (int k = 0; k < NK; k++) {
            float s = warp_sum(q.x * ksA[k] + q.y * ksB[k]);
            e[k] = __expf(s);                   // |s| ~ O(5): no max needed
            sum += e[k];
        }
        float inv = __fdividef(1.0f, sum);
        float oa = 0.f, ob = 0.f;
        #pragma unroll
        for (int k = 0; k < NK; k++) {
            float a = e[k] * inv;
            oa += a * vsA[k]; ob += a * vsB[k];
        }
        float2 o2v; o2v.x = oa; o2v.y = ob;
        *(float2*)(g_attn + (size_t)(g * 3 + t) * ATTN + h * HDIM + lane * 2) = o2v;
    }
}

// ---------------------------------------------------------------------------
// Kernel 4: output projection + residual.
//   out[row, f] = sum_a g_attn[row, a] * Wout[a, f] + b_out[f] + feat[row, f]
// ---------------------------------------------------------------------------
__global__ void __launch_bounds__(256) out_gemm(
    const float* __restrict__ Wout, const float* __restrict__ b_out,
    const float* __restrict__ feat, float* __restrict__ out)
{
    __shared__ float As[128][33];  // rows x kchunk (padded)
    __shared__ float Bs[32][33];   // k x col (padded)

    const int rBase = blockIdx.x * 128;
    const int tid = threadIdx.x;
    const int tx = tid & 7;        // col group (x4) -> 32 cols
    const int ty = tid >> 3;       // row group (x4) -> 128 rows

    float acc[4][4] = {};

    for (int kk = 0; kk < ATTN; kk += 32) {
        #pragma unroll
        for (int i = tid; i < 128 * 32; i += 256) {
            int r = i >> 5, k = i & 31;
            As[r][k] = g_attn[(size_t)(rBase + r) * ATTN + kk + k];
        }
        #pragma unroll
        for (int i = tid; i < 32 * 32; i += 256) {
            int k = i >> 5, c = i & 31;
            Bs[k][c] = Wout[(size_t)(kk + k) * GFD + c];
        }
        __syncthreads();
        #pragma unroll
        for (int k = 0; k < 32; k++) {
            float av[4], bv[4];
            #pragma unroll
            for (int i = 0; i < 4; i++) av[i] = As[ty * 4 + i][k];
            #pragma unroll
            for (int j = 0; j < 4; j++) bv[j] = Bs[k][tx * 4 + j];
            #pragma unroll
            for (int i = 0; i < 4; i++)
                #pragma unroll
                for (int j = 0; j < 4; j++) acc[i][j] += av[i] * bv[j];
        }
        __syncthreads();
    }
    #pragma unroll
    for (int i = 0; i < 4; i++) {
        int grow = rBase + ty * 4 + i;
        #pragma unroll
        for (int j = 0; j < 4; j++) {
            int col = tx * 4 + j;
            out[(size_t)grow * GFD + col] =
                acc[i][j] + b_out[col] + feat[(size_t)grow * GFD + col];
        }
    }
}

// ---------------------------------------------------------------------------
// Launch
// ---------------------------------------------------------------------------
extern "C" void kernel_launch(void* const* d_in, const int* in_sizes, int n_in,
                              void* d_out, int out_size)
{
    const float* means      = (const float*)d_in[0];
    const float* scales     = (const float*)d_in[1];
    const float* rotations  = (const float*)d_in[2];
    const float* features   = (const float*)d_in[3];
    const float* transforms = (const float*)d_in[4];
    const float* projection = (const float*)d_in[5];
    const float* image_feat = (const float*)d_in[6];
    const float* Wq         = (const float*)d_in[7];
    const float* Wk         = (const float*)d_in[8];
    const float* Wv         = (const float*)d_in[9];
    const float* W_off      = (const float*)d_in[10];
    const float* b_off      = (const float*)d_in[11];
    const float* Wout       = (const float*)d_in[12];
    const float* b_out      = (const float*)d_in[13];
    float* out = (float*)d_out;

    // 1) KV feature maps: [1024 x 4096] GEMM, written pixel-major fp16 interleaved
    kv_gemm<<<dim3(NPIX / 128, 1024 / 128), 256>>>(Wk, Wv, image_feat);
    // 2) Q projection: [24576 x 512]
    q_gemm<<<dim3(ATTN / 64, NROW / 64), 256>>>(features, Wq);
    // 3a) offsets -> resolved bilinear weights + corner offsets
    coord_kernel<<<NG, 256>>>(means, scales, rotations, transforms,
                              projection, W_off, b_off);
    // 3b) barrier-free gather + attention (one warp per (g,h))
    gather_attn<<<NG, 256>>>();
    // 4) output projection + bias + residual
    out_gemm<<<NROW / 128, 256>>>(Wout, b_out, features, out);
}

// round 13
// speedup vs baseline: 1.4604x; 1.0357x over previous
#include <cuda_runtime.h>
#include <cuda_fp16.h>
#include <math.h>

// ---------------------------------------------------------------------------
// Problem constants
//   G=8192 gaussians, BS=1, 3 tokens, GFD=32, ATTN=512, H=8 heads, HD=64
//   image_features [256,64,64], K = 12 sample points (6 fixed + 6 learned)
// ---------------------------------------------------------------------------
#define NG      8192
#define NROW    (NG*3)        // 24576 (gaussian,token) rows
#define ATTN    512
#define GFD     32
#define NHEAD   8
#define HDIM    64
#define IMGW    64
#define IMGH    64
#define NPIX    (IMGW*IMGH)   // 4096
#define CIMG    256
#define NK      12

// Scratch (static device globals: allocation-free per harness rules)
// g_kvh layout: per pixel, 256 channel-pairs; slot 2p = K half2 (ch 2p,2p+1),
//               slot 2p+1 = V half2.  One 8-byte load fetches K+V for a lane.
__device__ __half2 g_kvh[NPIX * 512];        // 8 MB, L2-resident
__device__ __half2 g_qh[NROW * ATTN / 2];    // q_full, fp16               (25 MB)
__device__ __half2 g_attnh[NROW * ATTN / 2]; // attention output, fp16     (25 MB)
__device__ uint4   g_wh[NG * NHEAD * NK];    // 4 corner weights, each replicated half2
__device__ int4    g_o4[NG * NHEAD * NK];    // clamped corner offsets (x512)

__constant__ float c_fix[6][3] = {
    {0.f,0.f,0.f},{1.f,0.f,0.f},{0.f,1.f,0.f},
    {0.f,0.f,1.f},{-1.f,0.f,0.f},{0.f,-1.f,0.f}};

__device__ __forceinline__ float sigm_clamped(float x) {
    x = fminf(fmaxf(x, -9.21f), 9.21f);
    return 1.0f / (1.0f + __expf(-x));
}

// 5-stage butterfly warp sum (redux.sync.f32 not available on sm_103 target)
__device__ __forceinline__ float warp_sum(float v) {
    #pragma unroll
    for (int o = 16; o > 0; o >>= 1) v += __shfl_xor_sync(0xffffffffu, v, o);
    return v;
}

// ---------------------------------------------------------------------------
// Kernel 1: KV maps.  C[a,pix] = sum_c Wkv[a,c] * img[c,pix]
//   a in [0,1024): rows 0..511 from Wk, 512..1023 from Wv.
//   Block tile 128(a) x 128(pix), thread tile 8x8, k-major smem.
//   Written transposed + fp16-packed + K/V-interleaved into g_kvh.
// ---------------------------------------------------------------------------
__global__ void __launch_bounds__(256) kv_gemm(
    const float* __restrict__ Wk, const float* __restrict__ Wv,
    const float* __restrict__ img)
{
    __shared__ float As[16][132];   // k x a (padded)
    __shared__ float Bs[16][132];   // k x pix (padded)

    const int aBase = blockIdx.y * 128;
    const int pBase = blockIdx.x * 128;
    const int tid = threadIdx.x;
    const int tx = tid & 15;        // pix group (x8)
    const int ty = tid >> 4;        // a group (x8)

    float acc[8][8] = {};

    for (int kk = 0; kk < CIMG; kk += 16) {
        #pragma unroll
        for (int i = tid; i < 128 * 16; i += 256) {
            int a = i >> 4, k = i & 15;
            int ga = aBase + a;
            float v = (ga < 512) ? Wk[ga * CIMG + kk + k]
                                 : Wv[(ga - 512) * CIMG + kk + k];
            As[k][a] = v;
        }
        #pragma unroll
        for (int i = tid; i < 16 * 128; i += 256) {
            int k = i >> 7, p = i & 127;
            Bs[k][p] = img[(kk + k) * NPIX + pBase + p];
        }
        __syncthreads();
        #pragma unroll
        for (int k = 0; k < 16; k++) {
            float av[8], bv[8];
            #pragma unroll
            for (int i = 0; i < 8; i++) av[i] = As[k][ty * 8 + i];
            #pragma unroll
            for (int j = 0; j < 8; j++) bv[j] = Bs[k][tx * 8 + j];
            #pragma unroll
            for (int i = 0; i < 8; i++)
                #pragma unroll
                for (int j = 0; j < 8; j++) acc[i][j] += av[i] * bv[j];
        }
        __syncthreads();
    }
    // Epilogue: pack to half2, interleaved K/V slots.
    const int paBase = (aBase >> 1) + ty * 4;   // global channel-pair index
    #pragma unroll
    for (int j = 0; j < 8; j++) {
        int pix = pBase + tx * 8 + j;
        #pragma unroll
        for (int p = 0; p < 4; p++) {
            int pa = paBase + p;
            int slot = (pa < 256) ? (2 * pa) : (2 * (pa - 256) + 1);
            g_kvh[(size_t)pix * 512 + slot] =
                __floats2half2_rn(acc[2 * p][j], acc[2 * p + 1][j]);
        }
    }
}

// ---------------------------------------------------------------------------
// Kernel 2: Q projection.  g_qh[row, a] = sum_f feat[row, f] * Wq[f, a] (fp16)
// ---------------------------------------------------------------------------
__global__ void __launch_bounds__(256) q_gemm(
    const float* __restrict__ feat, const float* __restrict__ Wq)
{
    __shared__ float As[64][33];   // rows x k
    __shared__ float Bs[32][64];   // k x cols

    const int rBase = blockIdx.y * 64;
    const int cBase = blockIdx.x * 64;
    const int tid = threadIdx.x;
    const int tx = tid & 15, ty = tid >> 4;

    #pragma unroll
    for (int i = tid; i < 64 * 32; i += 256) {
        int r = i >> 5, k = i & 31;
        As[r][k] = feat[(size_t)(rBase + r) * 32 + k];
    }
    #pragma unroll
    for (int i = tid; i < 32 * 64; i += 256) {
        int k = i >> 6, c = i & 63;
        Bs[k][c] = Wq[(size_t)k * ATTN + cBase + c];
    }
    __syncthreads();

    float acc[4][4] = {};
    #pragma unroll
    for (int k = 0; k < 32; k++) {
        float av[4], bv[4];
        #pragma unroll
        for (int i = 0; i < 4; i++) av[i] = As[ty * 4 + i][k];
        #pragma unroll
        for (int j = 0; j < 4; j++) bv[j] = Bs[k][tx * 4 + j];
        #pragma unroll
        for (int i = 0; i < 4; i++)
            #pragma unroll
            for (int j = 0; j < 4; j++) acc[i][j] += av[i] * bv[j];
    }
    // pack 4 halves per 8-byte store (index is even: cBase%64==0, tx*4 even)
    #pragma unroll
    for (int i = 0; i < 4; i++) {
        __half2 p0 = __floats2half2_rn(acc[i][0], acc[i][1]);
        __half2 p1 = __floats2half2_rn(acc[i][2], acc[i][3]);
        float2 st;
        *(__half2*)&st.x = p0;
        *(__half2*)&st.y = p1;
        *(float2*)(g_qh + (((size_t)(rBase + ty * 4 + i) * ATTN + cBase + tx * 4) >> 1)) = st;
    }
}

// ---------------------------------------------------------------------------
// Kernel 3a: coordinate precompute.
//   One block per gaussian, one warp per head. Computes OffsetNet logits, the
//   12 sample points, and fully-resolved bilinear corner weights (packed as
//   replicated half2) + clamped corner offsets.
// ---------------------------------------------------------------------------
__global__ void __launch_bounds__(256) coord_kernel(
    const float* __restrict__ means, const float* __restrict__ scales,
    const float* __restrict__ rots, const float* __restrict__ transforms,
    const float* __restrict__ proj, const float* __restrict__ W_off,
    const float* __restrict__ b_off)
{
    const int g = blockIdx.x;
    const int tid = threadIdx.x;
    const int h = tid >> 5;
    const int lane = tid & 31;

    __shared__ float sqm[NHEAD][HDIM];   // per-head token-mean query
    __shared__ float slog[NHEAD][18];    // offset logits
    __shared__ float sW[67 * 18];
    __shared__ float sb[18];
    __shared__ float sP[12];
    __shared__ float sMisc[16];          // 0-2 mean_w, 3-11 R(row major), 12-14 scales

    for (int i = tid; i < 67 * 18; i += 256) sW[i] = W_off[i];
    if (tid < 18) sb[tid] = b_off[tid];
    if (tid >= 32 && tid < 44) sP[tid - 32] = proj[tid - 32];
    if (tid == 64) {
        float mx = means[g * 3], my = means[g * 3 + 1], mz = means[g * 3 + 2];
        const float* T = transforms + (size_t)g * 16;
        sMisc[0] = T[0] * mx + T[1] * my + T[2]  * mz + T[3];
        sMisc[1] = T[4] * mx + T[5] * my + T[6]  * mz + T[7];
        sMisc[2] = T[8] * mx + T[9] * my + T[10] * mz + T[11];
        float qw = rots[g * 4], qx = rots[g * 4 + 1], qy = rots[g * 4 + 2], qz = rots[g * 4 + 3];
        float inv = rsqrtf(qw * qw + qx * qx + qy * qy + qz * qz);
        qw *= inv; qx *= inv; qy *= inv; qz *= inv;
        sMisc[3]  = 1.f - 2.f * (qy * qy + qz * qz);
        sMisc[4]  = 2.f * (qx * qy - qw * qz);
        sMisc[5]  = 2.f * (qx * qz + qw * qy);
        sMisc[6]  = 2.f * (qx * qy + qw * qz);
        sMisc[7]  = 1.f - 2.f * (qx * qx + qz * qz);
        sMisc[8]  = 2.f * (qy * qz - qw * qx);
        sMisc[9]  = 2.f * (qx * qz - qw * qy);
        sMisc[10] = 2.f * (qy * qz + qw * qx);
        sMisc[11] = 1.f - 2.f * (qx * qx + qy * qy);
        sMisc[12] = scales[g * 3]; sMisc[13] = scales[g * 3 + 1]; sMisc[14] = scales[g * 3 + 2];
    }

    // per-head token-mean query (2 channels per lane, from fp16 g_qh)
    {
        const __half2* qg = g_qh + ((((size_t)g * 3) * ATTN + h * HDIM) >> 1) + lane;
        float2 q0 = __half22float2(qg[0]);
        float2 q1 = __half22float2(qg[ATTN / 2]);
        float2 q2 = __half22float2(qg[ATTN]);
        sqm[h][lane * 2]     = (q0.x + q1.x + q2.x) * (1.0f / 3.0f);
        sqm[h][lane * 2 + 1] = (q0.y + q1.y + q2.y) * (1.0f / 3.0f);
    }
    __syncthreads();

    // offset logits: off_in = [mean_w(3), q_mean(64)] @ W_off + b_off
    if (lane < 18) {
        float acc = sb[lane] + sMisc[0] * sW[lane] + sMisc[1] * sW[18 + lane] + sMisc[2] * sW[36 + lane];
        #pragma unroll 8
        for (int c = 0; c < HDIM; c++) acc += sqm[h][c] * sW[(3 + c) * 18 + lane];
        slog[h][lane] = acc;
    }
    __syncwarp();

    if (lane < NK) {
        const int k = lane;
        float s0, s1, s2;
        if (k < 6) {
            s0 = c_fix[k][0]; s1 = c_fix[k][1]; s2 = c_fix[k][2];
        } else {
            int b = (k - 6) * 3;
            s0 = sigm_clamped(slog[h][b])     - 0.5f;
            s1 = sigm_clamped(slog[h][b + 1]) - 0.5f;
            s2 = sigm_clamped(slog[h][b + 2]) - 0.5f;
        }
        float o0 = s0 * sMisc[12], o1 = s1 * sMisc[13], o2 = s2 * sMisc[14];
        // world offset = R^T @ o + mean_w
        float wx = sMisc[3] * o0 + sMisc[6] * o1 + sMisc[9]  * o2 + sMisc[0];
        float wy = sMisc[4] * o0 + sMisc[7] * o1 + sMisc[10] * o2 + sMisc[1];
        float wz = sMisc[5] * o0 + sMisc[8] * o1 + sMisc[11] * o2 + sMisc[2];
        float p0 = sP[0] * wx + sP[1] * wy + sP[2]  * wz + sP[3];
        float p1 = sP[4] * wx + sP[5] * wy + sP[6]  * wz + sP[7];
        float p2 = sP[8] * wx + sP[9] * wy + sP[10] * wz + sP[11];
        float z = fmaxf(p2, 1e-5f);
        float xn = fminf(fmaxf(p0 / z * (1.0f / IMGW), 0.0f), 0.9999f);
        float yn = fminf(fmaxf(p1 / z * (1.0f / IMGH), 0.0f), 0.9999f);
        float x = xn * (float)IMGW - 0.5f;
        float y = yn * (float)IMGH - 0.5f;

        // Resolve bilinear sampling: weights (zeroed when OOB, replicated
        // half2) + clamped corner offsets in units of half2 (pixel * 512).
        float xf = floorf(x), yf = floorf(y);
        int x0 = (int)xf, y0 = (int)yf;
        float fx = x - xf, fy = y - yf;
        float w00 = (1.f - fx) * (1.f - fy), w10 = fx * (1.f - fy);
        float w01 = (1.f - fx) * fy,         w11 = fx * fy;
        int x1 = x0 + 1, y1 = y0 + 1;
        float vx0 = (x0 >= 0) ? 1.f : 0.f;
        float vx1 = (x1 <= IMGW - 1) ? 1.f : 0.f;
        float vy0 = (y0 >= 0) ? 1.f : 0.f;
        float vy1 = (y1 <= IMGH - 1) ? 1.f : 0.f;
        int cx0 = max(x0, 0), cx1 = min(x1, IMGW - 1);
        int cy0 = max(y0, 0), cy1 = min(y1, IMGH - 1);

        size_t idx = ((size_t)g * NHEAD + h) * NK + k;
        __half2 h00 = __float2half2_rn(w00 * vx0 * vy0);
        __half2 h10 = __float2half2_rn(w10 * vx1 * vy0);
        __half2 h01 = __float2half2_rn(w01 * vx0 * vy1);
        __half2 h11 = __float2half2_rn(w11 * vx1 * vy1);
        uint4 uw;
        uw.x = *(unsigned*)&h00;
        uw.y = *(unsigned*)&h10;
        uw.z = *(unsigned*)&h01;
        uw.w = *(unsigned*)&h11;
        g_wh[idx] = uw;
        int4 o4;
        o4.x = (cy0 * IMGW + cx0) * 512;
        o4.y = (cy0 * IMGW + cx1) * 512;
        o4.z = (cy1 * IMGW + cx0) * 512;
        o4.w = (cy1 * IMGW + cx1) * 512;
        g_o4[idx] = o4;
    }
}

// ---------------------------------------------------------------------------
// Kernel 3b: gather + attention.  ONE WARP per (gaussian, head).
//   Per corner: 1 LDG.64 + 2 HFMA2 (half2 accumulation, pre-packed half2
//   weights).  Butterfly score reduction in fp32, max-free softmax.
// ---------------------------------------------------------------------------
__global__ void __launch_bounds__(256) gather_attn()
{
    const int wid  = (blockIdx.x * 256 + threadIdx.x) >> 5;  // 0..65535
    const int lane = threadIdx.x & 31;
    const int g = wid >> 3;
    const int h = wid & 7;
    const int hidx2 = 2 * (h * 32 + lane);     // half2 offset within pixel record

    const uint4* __restrict__ wp = g_wh + (size_t)wid * NK;
    const int4*  __restrict__ op = g_o4 + (size_t)wid * NK;

    float ksA[NK], ksB[NK], vsA[NK], vsB[NK];

    #pragma unroll
    for (int k = 0; k < NK; k++) {
        uint4 uw = wp[k];                       // warp-uniform broadcast loads
        int4  o  = op[k];
        __half2 kacc = __floats2half2_rn(0.f, 0.f);
        __half2 vacc = __floats2half2_rn(0.f, 0.f);
        {
            float2 raw = *(const float2*)(g_kvh + o.x + hidx2);
            kacc = __hfma2(*(__half2*)&uw.x, *(__half2*)&raw.x, kacc);
            vacc = __hfma2(*(__half2*)&uw.x, *(__half2*)&raw.y, vacc);
        }
        {
            float2 raw = *(const float2*)(g_kvh + o.y + hidx2);
            kacc = __hfma2(*(__half2*)&uw.y, *(__half2*)&raw.x, kacc);
            vacc = __hfma2(*(__half2*)&uw.y, *(__half2*)&raw.y, vacc);
        }
        {
            float2 raw = *(const float2*)(g_kvh + o.z + hidx2);
            kacc = __hfma2(*(__half2*)&uw.z, *(__half2*)&raw.x, kacc);
            vacc = __hfma2(*(__half2*)&uw.z, *(__half2*)&raw.y, vacc);
        }
        {
            float2 raw = *(const float2*)(g_kvh + o.w + hidx2);
            kacc = __hfma2(*(__half2*)&uw.w, *(__half2*)&raw.x, kacc);
            vacc = __hfma2(*(__half2*)&uw.w, *(__half2*)&raw.y, vacc);
        }
        float2 kf = __half22float2(kacc);
        float2 vf = __half22float2(vacc);
        ksA[k] = kf.x; ksB[k] = kf.y;
        vsA[k] = vf.x; vsB[k] = vf.y;
    }

    const __half2* qg = g_qh + ((((size_t)g * 3) * ATTN + h * HDIM) >> 1) + lane;

    #pragma unroll
    for (int t = 0; t < 3; t++) {
        float2 q = __half22float2(qg[t * (ATTN / 2)]);
        q.x *= 0.125f; q.y *= 0.125f;          // fold HD^-0.5 into q
        float e[NK], sum = 0.f;
        #pragma unroll
        for (int k = 0; k < NK; k++) {
            float s = warp_sum(q.x * ksA[k] + q.y * ksB[k]);
            e[k] = __expf(s);                   // |s| ~ O(5): no max needed
            sum += e[k];
        }
        float inv = __fdividef(1.0f, sum);
        float oa = 0.f, ob = 0.f;
        #pragma unroll
        for (int k = 0; k < NK; k++) {
            float a = e[k] * inv;
            oa += a * vsA[k]; ob += a * vsB[k];
        }
        g_attnh[((((size_t)(g * 3 + t) * ATTN) + h * HDIM) >> 1) + lane] =
            __floats2half2_rn(oa, ob);
    }
}

// ---------------------------------------------------------------------------
// Kernel 4: output projection + residual.
//   out[row, f] = sum_a g_attnh[row, a] * Wout[a, f] + b_out[f] + feat[row, f]
// ---------------------------------------------------------------------------
__global__ void __launch_bounds__(256) out_gemm(
    const float* __restrict__ Wout, const float* __restrict__ b_out,
    const float* __restrict__ feat, float* __restrict__ out)
{
    __shared__ float As[128][34];  // rows x kchunk (padded, even stride)
    __shared__ float Bs[32][33];   // k x col (padded)

    const int rBase = blockIdx.x * 128;
    const int tid = threadIdx.x;
    const int tx = tid & 7;        // col group (x4) -> 32 cols
    const int ty = tid >> 3;       // row group (x4) -> 128 rows

    float acc[4][4] = {};

    for (int kk = 0; kk < ATTN; kk += 32) {
        #pragma unroll
        for (int i = tid; i < 128 * 16; i += 256) {
            int r = i >> 4, kp = i & 15;
            float2 v = __half22float2(
                g_attnh[((size_t)(rBase + r) * ATTN + kk + kp * 2) >> 1]);
            *(float2*)&As[r][kp * 2] = v;
        }
        #pragma unroll
        for (int i = tid; i < 32 * 32; i += 256) {
            int k = i >> 5, c = i & 31;
            Bs[k][c] = Wout[(size_t)(kk + k) * GFD + c];
        }
        __syncthreads();
        #pragma unroll
        for (int k = 0; k < 32; k++) {
            float av[4], bv[4];
            #pragma unroll
            for (int i = 0; i < 4; i++) av[i] = As[ty * 4 + i][k];
            #pragma unroll
            for (int j = 0; j < 4; j++) bv[j] = Bs[k][tx * 4 + j];
            #pragma unroll
            for (int i = 0; i < 4; i++)
                #pragma unroll
                for (int j = 0; j < 4; j++) acc[i][j] += av[i] * bv[j];
        }
        __syncthreads();
    }
    #pragma unroll
    for (int i = 0; i < 4; i++) {
        int grow = rBase + ty * 4 + i;
        #pragma unroll
        for (int j = 0; j < 4; j++) {
            int col = tx * 4 + j;
            out[(size_t)grow * GFD + col] =
                acc[i][j] + b_out[col] + feat[(size_t)grow * GFD + col];
        }
    }
}

// ---------------------------------------------------------------------------
// Launch
// ---------------------------------------------------------------------------
extern "C" void kernel_launch(void* const* d_in, const int* in_sizes, int n_in,
                              void* d_out, int out_size)
{
    const float* means      = (const float*)d_in[0];
    const float* scales     = (const float*)d_in[1];
    const float* rotations  = (const float*)d_in[2];
    const float* features   = (const float*)d_in[3];
    const float* transforms = (const float*)d_in[4];
    const float* projection = (const float*)d_in[5];
    const float* image_feat = (const float*)d_in[6];
    const float* Wq         = (const float*)d_in[7];
    const float* Wk         = (const float*)d_in[8];
    const float* Wv         = (const float*)d_in[9];
    const float* W_off      = (const float*)d_in[10];
    const float* b_off      = (const float*)d_in[11];
    const float* Wout       = (const float*)d_in[12];
    const float* b_out      = (const float*)d_in[13];
    float* out = (float*)d_out;

    // 1) KV feature maps: [1024 x 4096] GEMM, written pixel-major fp16 interleaved
    kv_gemm<<<dim3(NPIX / 128, 1024 / 128), 256>>>(Wk, Wv, image_feat);
    // 2) Q projection: [24576 x 512], fp16 output
    q_gemm<<<dim3(ATTN / 64, NROW / 64), 256>>>(features, Wq);
    // 3a) offsets -> resolved bilinear weights (half2) + corner offsets
    coord_kernel<<<NG, 256>>>(means, scales, rotations, transforms,
                              projection, W_off, b_off);
    // 3b) barrier-free gather + attention (one warp per (g,h))
    gather_attn<<<NG, 256>>>();
    // 4) output projection + bias + residual
    out_gemm<<<NROW / 128, 256>>>(Wout, b_out, features, out);
}

// round 14
// speedup vs baseline: 1.5955x; 1.0925x over previous
#include <cuda_runtime.h>
#include <cuda_fp16.h>
#include <math.h>

// ---------------------------------------------------------------------------
// Problem constants
//   G=8192 gaussians, BS=1, 3 tokens, GFD=32, ATTN=512, H=8 heads, HD=64
//   image_features [256,64,64], K = 12 sample points (6 fixed + 6 learned)
// ---------------------------------------------------------------------------
#define NG      8192
#define NROW    (NG*3)        // 24576 (gaussian,token) rows
#define ATTN    512
#define GFD     32
#define NHEAD   8
#define HDIM    64
#define IMGW    64
#define IMGH    64
#define NPIX    (IMGW*IMGH)   // 4096
#define CIMG    256
#define NK      12

// Scratch (static device globals: allocation-free per harness rules)
// g_kvh layout: per pixel, 256 channel-pairs; slot 2p = K half2 (ch 2p,2p+1),
//               slot 2p+1 = V half2.  One 8-byte load fetches K+V for a lane.
__device__ __half2 g_kvh[NPIX * 512];        // 8 MB, L2-resident
__device__ __half2 g_qh[NROW * ATTN / 2];    // q_full, fp16               (25 MB)
__device__ __half2 g_attnh[NROW * ATTN / 2]; // attention output, fp16     (25 MB)
__device__ uint4   g_wh[NG * NHEAD * NK];    // 4 corner weights, each replicated half2
__device__ int4    g_o4[NG * NHEAD * NK];    // clamped corner offsets (x512)

__constant__ float c_fix[6][3] = {
    {0.f,0.f,0.f},{1.f,0.f,0.f},{0.f,1.f,0.f},
    {0.f,0.f,1.f},{-1.f,0.f,0.f},{0.f,-1.f,0.f}};

__device__ __forceinline__ float sigm_clamped(float x) {
    x = fminf(fmaxf(x, -9.21f), 9.21f);
    return 1.0f / (1.0f + __expf(-x));
}

// 5-stage butterfly warp sum (redux.sync.f32 not available on sm_103 target)
__device__ __forceinline__ float warp_sum(float v) {
    #pragma unroll
    for (int o = 16; o > 0; o >>= 1) v += __shfl_xor_sync(0xffffffffu, v, o);
    return v;
}

// ---------------------------------------------------------------------------
// Kernel 1: KV maps.  C[a,pix] = sum_c Wkv[a,c] * img[c,pix]
//   a in [0,1024): rows 0..511 from Wk, 512..1023 from Wv.
//   Block tile 128(a) x 128(pix), thread tile 8x8, k-major smem.
//   Written transposed + fp16-packed + K/V-interleaved into g_kvh.
// ---------------------------------------------------------------------------
__global__ void __launch_bounds__(256) kv_gemm(
    const float* __restrict__ Wk, const float* __restrict__ Wv,
    const float* __restrict__ img)
{
    __shared__ float As[16][132];   // k x a (padded)
    __shared__ float Bs[16][132];   // k x pix (padded)

    const int aBase = blockIdx.y * 128;
    const int pBase = blockIdx.x * 128;
    const int tid = threadIdx.x;
    const int tx = tid & 15;        // pix group (x8)
    const int ty = tid >> 4;        // a group (x8)

    float acc[8][8] = {};

    for (int kk = 0; kk < CIMG; kk += 16) {
        #pragma unroll
        for (int i = tid; i < 128 * 16; i += 256) {
            int a = i >> 4, k = i & 15;
            int ga = aBase + a;
            float v = (ga < 512) ? Wk[ga * CIMG + kk + k]
                                 : Wv[(ga - 512) * CIMG + kk + k];
            As[k][a] = v;
        }
        #pragma unroll
        for (int i = tid; i < 16 * 128; i += 256) {
            int k = i >> 7, p = i & 127;
            Bs[k][p] = img[(kk + k) * NPIX + pBase + p];
        }
        __syncthreads();
        #pragma unroll
        for (int k = 0; k < 16; k++) {
            float av[8], bv[8];
            #pragma unroll
            for (int i = 0; i < 8; i++) av[i] = As[k][ty * 8 + i];
            #pragma unroll
            for (int j = 0; j < 8; j++) bv[j] = Bs[k][tx * 8 + j];
            #pragma unroll
            for (int i = 0; i < 8; i++)
                #pragma unroll
                for (int j = 0; j < 8; j++) acc[i][j] += av[i] * bv[j];
        }
        __syncthreads();
    }
    // Epilogue: pack to half2, interleaved K/V slots.
    const int paBase = (aBase >> 1) + ty * 4;   // global channel-pair index
    #pragma unroll
    for (int j = 0; j < 8; j++) {
        int pix = pBase + tx * 8 + j;
        #pragma unroll
        for (int p = 0; p < 4; p++) {
            int pa = paBase + p;
            int slot = (pa < 256) ? (2 * pa) : (2 * (pa - 256) + 1);
            g_kvh[(size_t)pix * 512 + slot] =
                __floats2half2_rn(acc[2 * p][j], acc[2 * p + 1][j]);
        }
    }
}

// ---------------------------------------------------------------------------
// Kernel 2: Q projection.  g_qh[row, a] = sum_f feat[row, f] * Wq[f, a] (fp16)
// ---------------------------------------------------------------------------
__global__ void __launch_bounds__(256) q_gemm(
    const float* __restrict__ feat, const float* __restrict__ Wq)
{
    __shared__ float As[64][33];   // rows x k
    __shared__ float Bs[32][64];   // k x cols

    const int rBase = blockIdx.y * 64;
    const int cBase = blockIdx.x * 64;
    const int tid = threadIdx.x;
    const int tx = tid & 15, ty = tid >> 4;

    #pragma unroll
    for (int i = tid; i < 64 * 32; i += 256) {
        int r = i >> 5, k = i & 31;
        As[r][k] = feat[(size_t)(rBase + r) * 32 + k];
    }
    #pragma unroll
    for (int i = tid; i < 32 * 64; i += 256) {
        int k = i >> 6, c = i & 63;
        Bs[k][c] = Wq[(size_t)k * ATTN + cBase + c];
    }
    __syncthreads();

    float acc[4][4] = {};
    #pragma unroll
    for (int k = 0; k < 32; k++) {
        float av[4], bv[4];
        #pragma unroll
        for (int i = 0; i < 4; i++) av[i] = As[ty * 4 + i][k];
        #pragma unroll
        for (int j = 0; j < 4; j++) bv[j] = Bs[k][tx * 4 + j];
        #pragma unroll
        for (int i = 0; i < 4; i++)
            #pragma unroll
            for (int j = 0; j < 4; j++) acc[i][j] += av[i] * bv[j];
    }
    // pack 4 halves per 8-byte store (index is even: cBase%64==0, tx*4 even)
    #pragma unroll
    for (int i = 0; i < 4; i++) {
        __half2 p0 = __floats2half2_rn(acc[i][0], acc[i][1]);
        __half2 p1 = __floats2half2_rn(acc[i][2], acc[i][3]);
        float2 st;
        *(__half2*)&st.x = p0;
        *(__half2*)&st.y = p1;
        *(float2*)(g_qh + (((size_t)(rBase + ty * 4 + i) * ATTN + cBase + tx * 4) >> 1)) = st;
    }
}

// ---------------------------------------------------------------------------
// Kernel 3a: coordinate precompute.
//   One block per gaussian, one warp per head. Computes OffsetNet logits, the
//   12 sample points, and fully-resolved bilinear corner weights (packed as
//   replicated half2) + clamped corner offsets.
// ---------------------------------------------------------------------------
__global__ void __launch_bounds__(256) coord_kernel(
    const float* __restrict__ means, const float* __restrict__ scales,
    const float* __restrict__ rots, const float* __restrict__ transforms,
    const float* __restrict__ proj, const float* __restrict__ W_off,
    const float* __restrict__ b_off)
{
    const int g = blockIdx.x;
    const int tid = threadIdx.x;
    const int h = tid >> 5;
    const int lane = tid & 31;

    __shared__ float sqm[NHEAD][HDIM];   // per-head token-mean query
    __shared__ float slog[NHEAD][18];    // offset logits
    __shared__ float sW[67 * 18];
    __shared__ float sb[18];
    __shared__ float sP[12];
    __shared__ float sMisc[16];          // 0-2 mean_w, 3-11 R(row major), 12-14 scales

    for (int i = tid; i < 67 * 18; i += 256) sW[i] = W_off[i];
    if (tid < 18) sb[tid] = b_off[tid];
    if (tid >= 32 && tid < 44) sP[tid - 32] = proj[tid - 32];
    if (tid == 64) {
        float mx = means[g * 3], my = means[g * 3 + 1], mz = means[g * 3 + 2];
        const float* T = transforms + (size_t)g * 16;
        sMisc[0] = T[0] * mx + T[1] * my + T[2]  * mz + T[3];
        sMisc[1] = T[4] * mx + T[5] * my + T[6]  * mz + T[7];
        sMisc[2] = T[8] * mx + T[9] * my + T[10] * mz + T[11];
        float qw = rots[g * 4], qx = rots[g * 4 + 1], qy = rots[g * 4 + 2], qz = rots[g * 4 + 3];
        float inv = rsqrtf(qw * qw + qx * qx + qy * qy + qz * qz);
        qw *= inv; qx *= inv; qy *= inv; qz *= inv;
        sMisc[3]  = 1.f - 2.f * (qy * qy + qz * qz);
        sMisc[4]  = 2.f * (qx * qy - qw * qz);
        sMisc[5]  = 2.f * (qx * qz + qw * qy);
        sMisc[6]  = 2.f * (qx * qy + qw * qz);
        sMisc[7]  = 1.f - 2.f * (qx * qx + qz * qz);
        sMisc[8]  = 2.f * (qy * qz - qw * qx);
        sMisc[9]  = 2.f * (qx * qz - qw * qy);
        sMisc[10] = 2.f * (qy * qz + qw * qx);
        sMisc[11] = 1.f - 2.f * (qx * qx + qy * qy);
        sMisc[12] = scales[g * 3]; sMisc[13] = scales[g * 3 + 1]; sMisc[14] = scales[g * 3 + 2];
    }

    // per-head token-mean query (2 channels per lane, from fp16 g_qh)
    {
        const __half2* qg = g_qh + ((((size_t)g * 3) * ATTN + h * HDIM) >> 1) + lane;
        float2 q0 = __half22float2(qg[0]);
        float2 q1 = __half22float2(qg[ATTN / 2]);
        float2 q2 = __half22float2(qg[ATTN]);
        sqm[h][lane * 2]     = (q0.x + q1.x + q2.x) * (1.0f / 3.0f);
        sqm[h][lane * 2 + 1] = (q0.y + q1.y + q2.y) * (1.0f / 3.0f);
    }
    __syncthreads();

    // offset logits: off_in = [mean_w(3), q_mean(64)] @ W_off + b_off
    if (lane < 18) {
        float acc = sb[lane] + sMisc[0] * sW[lane] + sMisc[1] * sW[18 + lane] + sMisc[2] * sW[36 + lane];
        #pragma unroll 8
        for (int c = 0; c < HDIM; c++) acc += sqm[h][c] * sW[(3 + c) * 18 + lane];
        slog[h][lane] = acc;
    }
    __syncwarp();

    if (lane < NK) {
        const int k = lane;
        float s0, s1, s2;
        if (k < 6) {
            s0 = c_fix[k][0]; s1 = c_fix[k][1]; s2 = c_fix[k][2];
        } else {
            int b = (k - 6) * 3;
            s0 = sigm_clamped(slog[h][b])     - 0.5f;
            s1 = sigm_clamped(slog[h][b + 1]) - 0.5f;
            s2 = sigm_clamped(slog[h][b + 2]) - 0.5f;
        }
        float o0 = s0 * sMisc[12], o1 = s1 * sMisc[13], o2 = s2 * sMisc[14];
        // world offset = R^T @ o + mean_w
        float wx = sMisc[3] * o0 + sMisc[6] * o1 + sMisc[9]  * o2 + sMisc[0];
        float wy = sMisc[4] * o0 + sMisc[7] * o1 + sMisc[10] * o2 + sMisc[1];
        float wz = sMisc[5] * o0 + sMisc[8] * o1 + sMisc[11] * o2 + sMisc[2];
        float p0 = sP[0] * wx + sP[1] * wy + sP[2]  * wz + sP[3];
        float p1 = sP[4] * wx + sP[5] * wy + sP[6]  * wz + sP[7];
        float p2 = sP[8] * wx + sP[9] * wy + sP[10] * wz + sP[11];
        float z = fmaxf(p2, 1e-5f);
        float xn = fminf(fmaxf(p0 / z * (1.0f / IMGW), 0.0f), 0.9999f);
        float yn = fminf(fmaxf(p1 / z * (1.0f / IMGH), 0.0f), 0.9999f);
        float x = xn * (float)IMGW - 0.5f;
        float y = yn * (float)IMGH - 0.5f;

        // Resolve bilinear sampling: weights (zeroed when OOB, replicated
        // half2) + clamped corner offsets in units of half2 (pixel * 512).
        float xf = floorf(x), yf = floorf(y);
        int x0 = (int)xf, y0 = (int)yf;
        float fx = x - xf, fy = y - yf;
        float w00 = (1.f - fx) * (1.f - fy), w10 = fx * (1.f - fy);
        float w01 = (1.f - fx) * fy,         w11 = fx * fy;
        int x1 = x0 + 1, y1 = y0 + 1;
        float vx0 = (x0 >= 0) ? 1.f : 0.f;
        float vx1 = (x1 <= IMGW - 1) ? 1.f : 0.f;
        float vy0 = (y0 >= 0) ? 1.f : 0.f;
        float vy1 = (y1 <= IMGH - 1) ? 1.f : 0.f;
        int cx0 = max(x0, 0), cx1 = min(x1, IMGW - 1);
        int cy0 = max(y0, 0), cy1 = min(y1, IMGH - 1);

        size_t idx = ((size_t)g * NHEAD + h) * NK + k;
        __half2 h00 = __float2half2_rn(w00 * vx0 * vy0);
        __half2 h10 = __float2half2_rn(w10 * vx1 * vy0);
        __half2 h01 = __float2half2_rn(w01 * vx0 * vy1);
        __half2 h11 = __float2half2_rn(w11 * vx1 * vy1);
        uint4 uw;
        uw.x = *(unsigned*)&h00;
        uw.y = *(unsigned*)&h10;
        uw.z = *(unsigned*)&h01;
        uw.w = *(unsigned*)&h11;
        g_wh[idx] = uw;
        int4 o4;
        o4.x = (cy0 * IMGW + cx0) * 512;
        o4.y = (cy0 * IMGW + cx1) * 512;
        o4.z = (cy1 * IMGW + cx0) * 512;
        o4.w = (cy1 * IMGW + cx1) * 512;
        g_o4[idx] = o4;
    }
}

// ---------------------------------------------------------------------------
// Kernel 3b: gather + attention.  ONE WARP per (gaussian, head).
//   ONLINE softmax accumulation: K/V are consumed inside the k-loop (no
//   12-wide register staging arrays) -> ~40 regs -> 2x occupancy to hide
//   SHFL-butterfly latency.  All 3 tokens processed per k (shared K/V).
// ---------------------------------------------------------------------------
__global__ void __launch_bounds__(256, 4) gather_attn()
{
    const int wid  = (blockIdx.x * 256 + threadIdx.x) >> 5;  // 0..65535
    const int lane = threadIdx.x & 31;
    const int g = wid >> 3;
    const int h = wid & 7;
    const int hidx2 = 2 * (h * 32 + lane);     // half2 offset within pixel record

    const uint4* __restrict__ wp = g_wh + (size_t)wid * NK;
    const int4*  __restrict__ op = g_o4 + (size_t)wid * NK;

    // Pre-load the 3 token queries (2 channels/lane), fold in HD^-0.5.
    const __half2* qg = g_qh + ((((size_t)g * 3) * ATTN + h * HDIM) >> 1) + lane;
    float2 q0 = __half22float2(qg[0]);
    float2 q1 = __half22float2(qg[ATTN / 2]);
    float2 q2 = __half22float2(qg[ATTN]);
    q0.x *= 0.125f; q0.y *= 0.125f;
    q1.x *= 0.125f; q1.y *= 0.125f;
    q2.x *= 0.125f; q2.y *= 0.125f;

    float sum0 = 0.f, sum1 = 0.f, sum2 = 0.f;
    float oa0 = 0.f, ob0 = 0.f, oa1 = 0.f, ob1 = 0.f, oa2 = 0.f, ob2 = 0.f;

    #pragma unroll
    for (int k = 0; k < NK; k++) {
        uint4 uw = wp[k];                       // warp-uniform broadcast loads
        int4  o  = op[k];
        __half2 kacc = __floats2half2_rn(0.f, 0.f);
        __half2 vacc = __floats2half2_rn(0.f, 0.f);
        {
            float2 raw = *(const float2*)(g_kvh + o.x + hidx2);
            kacc = __hfma2(*(__half2*)&uw.x, *(__half2*)&raw.x, kacc);
            vacc = __hfma2(*(__half2*)&uw.x, *(__half2*)&raw.y, vacc);
        }
        {
            float2 raw = *(const float2*)(g_kvh + o.y + hidx2);
            kacc = __hfma2(*(__half2*)&uw.y, *(__half2*)&raw.x, kacc);
            vacc = __hfma2(*(__half2*)&uw.y, *(__half2*)&raw.y, vacc);
        }
        {
            float2 raw = *(const float2*)(g_kvh + o.z + hidx2);
            kacc = __hfma2(*(__half2*)&uw.z, *(__half2*)&raw.x, kacc);
            vacc = __hfma2(*(__half2*)&uw.z, *(__half2*)&raw.y, vacc);
        }
        {
            float2 raw = *(const float2*)(g_kvh + o.w + hidx2);
            kacc = __hfma2(*(__half2*)&uw.w, *(__half2*)&raw.x, kacc);
            vacc = __hfma2(*(__half2*)&uw.w, *(__half2*)&raw.y, vacc);
        }
        float2 kf = __half22float2(kacc);
        float2 vf = __half22float2(vacc);

        // 3 independent butterflies (ILP); online exp-weighted accumulation.
        float s0 = warp_sum(q0.x * kf.x + q0.y * kf.y);
        float s1 = warp_sum(q1.x * kf.x + q1.y * kf.y);
        float s2 = warp_sum(q2.x * kf.x + q2.y * kf.y);
        float e0 = __expf(s0);                  // |s| ~ O(5): no max needed
        float e1 = __expf(s1);
        float e2 = __expf(s2);
        sum0 += e0; oa0 += e0 * vf.x; ob0 += e0 * vf.y;
        sum1 += e1; oa1 += e1 * vf.x; ob1 += e1 * vf.y;
        sum2 += e2; oa2 += e2 * vf.x; ob2 += e2 * vf.y;
    }

    const size_t obase = (((size_t)g * 3) * ATTN + h * HDIM) / 2 + lane;
    float i0 = __fdividef(1.0f, sum0);
    float i1 = __fdividef(1.0f, sum1);
    float i2 = __fdividef(1.0f, sum2);
    g_attnh[obase]            = __floats2half2_rn(oa0 * i0, ob0 * i0);
    g_attnh[obase + ATTN / 2] = __floats2half2_rn(oa1 * i1, ob1 * i1);
    g_attnh[obase + ATTN]     = __floats2half2_rn(oa2 * i2, ob2 * i2);
}

// ---------------------------------------------------------------------------
// Kernel 4: output projection + residual.
//   out[row, f] = sum_a g_attnh[row, a] * Wout[a, f] + b_out[f] + feat[row, f]
// ---------------------------------------------------------------------------
__global__ void __launch_bounds__(256) out_gemm(
    const float* __restrict__ Wout, const float* __restrict__ b_out,
    const float* __restrict__ feat, float* __restrict__ out)
{
    __shared__ float As[128][34];  // rows x kchunk (padded, even stride)
    __shared__ float Bs[32][33];   // k x col (padded)

    const int rBase = blockIdx.x * 128;
    const int tid = threadIdx.x;
    const int tx = tid & 7;        // col group (x4) -> 32 cols
    const int ty = tid >> 3;       // row group (x4) -> 128 rows

    float acc[4][4] = {};

    for (int kk = 0; kk < ATTN; kk += 32) {
        #pragma unroll
        for (int i = tid; i < 128 * 16; i += 256) {
            int r = i >> 4, kp = i & 15;
            float2 v = __half22float2(
                g_attnh[((size_t)(rBase + r) * ATTN + kk + kp * 2) >> 1]);
            *(float2*)&As[r][kp * 2] = v;
        }
        #pragma unroll
        for (int i = tid; i < 32 * 32; i += 256) {
            int k = i >> 5, c = i & 31;
            Bs[k][c] = Wout[(size_t)(kk + k) * GFD + c];
        }
        __syncthreads();
        #pragma unroll
        for (int k = 0; k < 32; k++) {
            float av[4], bv[4];
            #pragma unroll
            for (int i = 0; i < 4; i++) av[i] = As[ty * 4 + i][k];
            #pragma unroll
            for (int j = 0; j < 4; j++) bv[j] = Bs[k][tx * 4 + j];
            #pragma unroll
            for (int i = 0; i < 4; i++)
                #pragma unroll
                for (int j = 0; j < 4; j++) acc[i][j] += av[i] * bv[j];
        }
        __syncthreads();
    }
    #pragma unroll
    for (int i = 0; i < 4; i++) {
        int grow = rBase + ty * 4 + i;
        #pragma unroll
        for (int j = 0; j < 4; j++) {
            int col = tx * 4 + j;
            out[(size_t)grow * GFD + col] =
                acc[i][j] + b_out[col] + feat[(size_t)grow * GFD + col];
        }
    }
}

// ---------------------------------------------------------------------------
// Launch
// ---------------------------------------------------------------------------
extern "C" void kernel_launch(void* const* d_in, const int* in_sizes, int n_in,
                              void* d_out, int out_size)
{
    const float* means      = (const float*)d_in[0];
    const float* scales     = (const float*)d_in[1];
    const float* rotations  = (const float*)d_in[2];
    const float* features   = (const float*)d_in[3];
    const float* transforms = (const float*)d_in[4];
    const float* projection = (const float*)d_in[5];
    const float* image_feat = (const float*)d_in[6];
    const float* Wq         = (const float*)d_in[7];
    const float* Wk         = (const float*)d_in[8];
    const float* Wv         = (const float*)d_in[9];
    const float* W_off      = (const float*)d_in[10];
    const float* b_off      = (const float*)d_in[11];
    const float* Wout       = (const float*)d_in[12];
    const float* b_out      = (const float*)d_in[13];
    float* out = (float*)d_out;

    // 1) KV feature maps: [1024 x 4096] GEMM, written pixel-major fp16 interleaved
    kv_gemm<<<dim3(NPIX / 128, 1024 / 128), 256>>>(Wk, Wv, image_feat);
    // 2) Q projection: [24576 x 512], fp16 output
    q_gemm<<<dim3(ATTN / 64, NROW / 64), 256>>>(features, Wq);
    // 3a) offsets -> resolved bilinear weights (half2) + corner offsets
    coord_kernel<<<NG, 256>>>(means, scales, rotations, transforms,
                              projection, W_off, b_off);
    // 3b) barrier-free gather + attention, online softmax (one warp per (g,h))
    gather_attn<<<NG, 256>>>();
    // 4) output projection + bias + residual
    out_gemm<<<NROW / 128, 256>>>(Wout, b_out, features, out);
}